// round 1
// baseline (speedup 1.0000x reference)
#include <cuda_runtime.h>
#include <math.h>

#define S_TOK 3872
#define C_DIM 1536
#define NHEAD 12
#define DHEAD 128
#define HALF  64
#define T_DIM 8
#define H_DIM 22
#define W_DIM 22

// ---------------- scratch (device globals; no runtime allocation) ----------------
__device__ float g_xn[S_TOK * C_DIM];
__device__ float g_q [S_TOK * C_DIM];
__device__ float g_k [S_TOK * C_DIM];
__device__ float g_v [S_TOK * C_DIM];
__device__ float g_o [S_TOK * C_DIM];
__device__ float g_cos[S_TOK * HALF];
__device__ float g_sin[S_TOK * HALF];

// ---------------- kernel 1: layernorm + (C,S) -> (S,C) transpose ----------------
// x layout: x[c*S + s]. Block handles 32 s-values. All global accesses coalesced.
__global__ void __launch_bounds__(256) ln_transpose_kernel(const float* __restrict__ x) {
    int s0 = blockIdx.x * 32;
    int sl = threadIdx.x & 31;   // s lane
    int cg = threadIdx.x >> 5;   // c group 0..7

    float sum = 0.f, sq = 0.f;
    for (int c = cg; c < C_DIM; c += 8) {
        float v = x[c * S_TOK + s0 + sl];
        sum += v; sq += v * v;
    }
    __shared__ float ssum[8][32], ssq[8][32];
    ssum[cg][sl] = sum; ssq[cg][sl] = sq;
    __syncthreads();

    __shared__ float mean_s[32], rstd_s[32];
    if (cg == 0) {
        float a = 0.f, b = 0.f;
        #pragma unroll
        for (int g = 0; g < 8; g++) { a += ssum[g][sl]; b += ssq[g][sl]; }
        float m = a / C_DIM;
        float var = b / C_DIM - m * m;
        mean_s[sl] = m;
        rstd_s[sl] = rsqrtf(var + 1e-6f);
    }
    __syncthreads();

    __shared__ float tile[32][33];
    for (int c0 = 0; c0 < C_DIM; c0 += 32) {
        #pragma unroll
        for (int r = 0; r < 4; r++) {
            int cl = cg + 8 * r;
            tile[cl][sl] = x[(c0 + cl) * S_TOK + s0 + sl];
        }
        __syncthreads();
        #pragma unroll
        for (int r = 0; r < 4; r++) {
            int srow = cg + 8 * r;
            g_xn[(s0 + srow) * C_DIM + c0 + sl] =
                (tile[sl][srow] - mean_s[srow]) * rstd_s[srow];
        }
        __syncthreads();
    }
}

// ---------------- kernel 2: RoPE cos/sin table (fp64, matches reference) ----------------
__global__ void rope_table_kernel() {
    int idx = blockIdx.x * blockDim.x + threadIdx.x;
    if (idx >= S_TOK * HALF) return;
    int s = idx >> 6, j = idx & 63;
    int t  = s / (H_DIM * W_DIM);
    int rem = s % (H_DIM * W_DIM);
    int hh = rem / W_DIM, ww = rem % W_DIM;
    const double LT = log(10000.0);
    double a;
    if (j < 22)      a = (double)t  * exp(-(double)j        / 22.0 * LT);
    else if (j < 43) a = (double)hh * exp(-(double)(j - 22) / 21.0 * LT);
    else             a = (double)ww * exp(-(double)(j - 43) / 21.0 * LT);
    g_cos[idx] = (float)cos(a);
    g_sin[idx] = (float)sin(a);
}

// ---------------- shared GEMM core: out(128x128 tile) = A(M,K) @ B(N,K)^T ----------------
// K = C_DIM for all uses. 256 threads, 8x8 microtile per thread.
__device__ __forceinline__ void gemm_core(const float* __restrict__ A,
                                          const float* __restrict__ B,
                                          int m0, int n0, float (&acc)[8][8]) {
    __shared__ float As[16][128];
    __shared__ float Bs[16][128];
    int tid = threadIdx.x;
    int r  = tid >> 2;            // 0..63
    int c4 = (tid & 3) << 2;      // 0,4,8,12
    int tx = tid & 15, ty = tid >> 4;

    for (int k0 = 0; k0 < C_DIM; k0 += 16) {
        #pragma unroll
        for (int p = 0; p < 2; p++) {
            int m = r + p * 64;
            float4 va = (m0 + m < S_TOK)
                ? *(const float4*)&A[(size_t)(m0 + m) * C_DIM + k0 + c4]
                : make_float4(0.f, 0.f, 0.f, 0.f);
            As[c4 + 0][m] = va.x; As[c4 + 1][m] = va.y;
            As[c4 + 2][m] = va.z; As[c4 + 3][m] = va.w;
            float4 vb = *(const float4*)&B[(size_t)(n0 + m) * C_DIM + k0 + c4];
            Bs[c4 + 0][m] = vb.x; Bs[c4 + 1][m] = vb.y;
            Bs[c4 + 2][m] = vb.z; Bs[c4 + 3][m] = vb.w;
        }
        __syncthreads();
        #pragma unroll
        for (int kk = 0; kk < 16; kk++) {
            float a[8], b[8];
            *(float4*)&a[0] = *(float4*)&As[kk][ty * 8];
            *(float4*)&a[4] = *(float4*)&As[kk][ty * 8 + 4];
            *(float4*)&b[0] = *(float4*)&Bs[kk][tx * 8];
            *(float4*)&b[4] = *(float4*)&Bs[kk][tx * 8 + 4];
            #pragma unroll
            for (int i = 0; i < 8; i++)
                #pragma unroll
                for (int j = 0; j < 8; j++)
                    acc[i][j] += a[i] * b[j];
        }
        __syncthreads();
    }
}

// ---------------- kernel 3: Q/K/V projections ----------------
__global__ void __launch_bounds__(256) gemm_qkv_kernel(
    const float* __restrict__ Wq, const float* __restrict__ bq,
    const float* __restrict__ Wk, const float* __restrict__ bk,
    const float* __restrict__ Wv, const float* __restrict__ bv) {
    const float *Wm, *bias; float* out;
    if (blockIdx.z == 0)      { Wm = Wq; bias = bq; out = g_q; }
    else if (blockIdx.z == 1) { Wm = Wk; bias = bk; out = g_k; }
    else                      { Wm = Wv; bias = bv; out = g_v; }

    int m0 = blockIdx.y * 128, n0 = blockIdx.x * 128;
    float acc[8][8];
    #pragma unroll
    for (int i = 0; i < 8; i++)
        #pragma unroll
        for (int j = 0; j < 8; j++) acc[i][j] = 0.f;

    gemm_core(g_xn, Wm, m0, n0, acc);

    int tx = threadIdx.x & 15, ty = threadIdx.x >> 4;
    #pragma unroll
    for (int i = 0; i < 8; i++) {
        int m = m0 + ty * 8 + i;
        if (m < S_TOK) {
            #pragma unroll
            for (int j = 0; j < 8; j++) {
                int n = n0 + tx * 8 + j;
                out[(size_t)m * C_DIM + n] = acc[i][j] + bias[n];
            }
        }
    }
}

// ---------------- kernel 4: RMSNorm (over full C) + RoPE per head, in-place ----------------
__global__ void __launch_bounds__(256) rms_rope_kernel(const float* __restrict__ gq,
                                                       const float* __restrict__ gk) {
    int s = blockIdx.x;
    float* data    = (blockIdx.y == 0) ? g_q : g_k;
    const float* g = (blockIdx.y == 0) ? gq  : gk;

    float ss = 0.f;
    for (int c = threadIdx.x; c < C_DIM; c += 256) {
        float v = data[(size_t)s * C_DIM + c];
        ss += v * v;
    }
    __shared__ float red[256];
    red[threadIdx.x] = ss;
    __syncthreads();
    for (int off = 128; off > 0; off >>= 1) {
        if (threadIdx.x < off) red[threadIdx.x] += red[threadIdx.x + off];
        __syncthreads();
    }
    float rs = rsqrtf(red[0] / C_DIM + 1e-6f);

    for (int p = threadIdx.x; p < NHEAD * HALF; p += 256) {
        int head = p >> 6, j = p & 63;
        int cr = head * DHEAD + 2 * j, ci = cr + 1;
        float xr = data[(size_t)s * C_DIM + cr] * rs * g[cr];
        float xi = data[(size_t)s * C_DIM + ci] * rs * g[ci];
        float co = g_cos[s * HALF + j], si = g_sin[s * HALF + j];
        data[(size_t)s * C_DIM + cr] = xr * co - xi * si;
        data[(size_t)s * C_DIM + ci] = xr * si + xi * co;
    }
}

// ---------------- kernel 5: flash attention ----------------
// Grid: (ceil(S/64), NH). 256 threads. BQ=BK=64, d=128. Online softmax.
#define QROW 132   // 128 + 4 pad, keeps float4 alignment (528B rows)
#define SROW 65

extern __shared__ __align__(16) float fsm[];

__global__ void __launch_bounds__(256) flash_kernel() {
    float* Qs   = fsm;                 // [64][132]
    float* Ks   = Qs  + 64 * QROW;     // [64][132]
    float* Vs   = Ks  + 64 * QROW;     // [64][132]
    float* Ssm  = Vs  + 64 * QROW;     // [64][65]
    float* red  = Ssm + 64 * SROW;     // [64][4]
    float* msm  = red + 256;           // [64]
    float* lsm  = msm + 64;            // [64]
    float* alsm = lsm + 64;            // [64]

    int q0 = blockIdx.x * 64;
    int h  = blockIdx.y;
    int tid = threadIdx.x;
    int tx = tid & 15, ty = tid >> 4;
    const float scale = 0.08838834764831845f;  // 1/sqrt(128)

    // load Q tile (coalesced over d)
    #pragma unroll 4
    for (int r = 0; r < 32; r++) {
        int idx = r * 256 + tid;
        int qi = idx >> 7, d = idx & 127;
        Qs[qi * QROW + d] = (q0 + qi < S_TOK)
            ? g_q[(size_t)(q0 + qi) * C_DIM + h * DHEAD + d] : 0.f;
    }
    if (tid < 64) { msm[tid] = -1e30f; lsm[tid] = 0.f; }
    __syncthreads();

    float acc[4][8];
    #pragma unroll
    for (int i = 0; i < 4; i++)
        #pragma unroll
        for (int j = 0; j < 8; j++) acc[i][j] = 0.f;

    for (int k0 = 0; k0 < S_TOK; k0 += 64) {
        // load K,V tiles
        #pragma unroll 4
        for (int r = 0; r < 32; r++) {
            int idx = r * 256 + tid;
            int ki = idx >> 7, d = idx & 127;
            bool ok = (k0 + ki < S_TOK);
            Ks[ki * QROW + d] = ok ? g_k[(size_t)(k0 + ki) * C_DIM + h * DHEAD + d] : 0.f;
            Vs[ki * QROW + d] = ok ? g_v[(size_t)(k0 + ki) * C_DIM + h * DHEAD + d] : 0.f;
        }
        __syncthreads();

        // ---- scores: 4x4 microtile (q rows ty*4+i, k cols tx*4+j) ----
        float sc[4][4];
        #pragma unroll
        for (int i = 0; i < 4; i++)
            #pragma unroll
            for (int j = 0; j < 4; j++) sc[i][j] = 0.f;

        #pragma unroll
        for (int dd = 0; dd < 128; dd += 4) {
            float4 a[4], b[4];
            #pragma unroll
            for (int i = 0; i < 4; i++) a[i] = *(float4*)&Qs[(ty * 4 + i) * QROW + dd];
            #pragma unroll
            for (int j = 0; j < 4; j++) b[j] = *(float4*)&Ks[(tx * 4 + j) * QROW + dd];
            #pragma unroll
            for (int i = 0; i < 4; i++)
                #pragma unroll
                for (int j = 0; j < 4; j++)
                    sc[i][j] += a[i].x * b[j].x + a[i].y * b[j].y
                              + a[i].z * b[j].z + a[i].w * b[j].w;
        }
        #pragma unroll
        for (int i = 0; i < 4; i++)
            #pragma unroll
            for (int j = 0; j < 4; j++) {
                int kg = k0 + tx * 4 + j;
                Ssm[(ty * 4 + i) * SROW + tx * 4 + j] =
                    (kg < S_TOK) ? sc[i][j] * scale : -1e30f;
            }
        __syncthreads();

        // ---- online softmax stats (4 threads per row) ----
        int row = tid >> 2, part = tid & 3;
        float mx = -1e30f;
        #pragma unroll
        for (int u = 0; u < 16; u++)
            mx = fmaxf(mx, Ssm[row * SROW + part * 16 + u]);
        red[row * 4 + part] = mx;
        __syncthreads();
        if (part == 0) {
            float m_old = msm[row];
            float mn = fmaxf(fmaxf(red[row * 4], red[row * 4 + 1]),
                             fmaxf(red[row * 4 + 2], red[row * 4 + 3]));
            mn = fmaxf(m_old, mn);
            alsm[row] = __expf(m_old - mn);
            msm[row] = mn;
        }
        __syncthreads();
        float mrow = msm[row];
        float psum = 0.f;
        #pragma unroll
        for (int u = 0; u < 16; u++) {
            float pv = __expf(Ssm[row * SROW + part * 16 + u] - mrow);
            Ssm[row * SROW + part * 16 + u] = pv;
            psum += pv;
        }
        red[row * 4 + part] = psum;
        __syncthreads();
        if (part == 0) {
            lsm[row] = lsm[row] * alsm[row]
                     + red[row * 4] + red[row * 4 + 1]
                     + red[row * 4 + 2] + red[row * 4 + 3];
        }

        // ---- PV: 4x8 microtile (q rows ty*4+i, d cols tx*8+j) ----
        float al[4];
        #pragma unroll
        for (int i = 0; i < 4; i++) al[i] = alsm[ty * 4 + i];
        #pragma unroll
        for (int i = 0; i < 4; i++)
            #pragma unroll
            for (int j = 0; j < 8; j++) acc[i][j] *= al[i];

        #pragma unroll 4
        for (int kk = 0; kk < 64; kk++) {
            float vv[8];
            *(float4*)&vv[0] = *(float4*)&Vs[kk * QROW + tx * 8];
            *(float4*)&vv[4] = *(float4*)&Vs[kk * QROW + tx * 8 + 4];
            #pragma unroll
            for (int i = 0; i < 4; i++) {
                float p = Ssm[(ty * 4 + i) * SROW + kk];
                #pragma unroll
                for (int j = 0; j < 8; j++) acc[i][j] += p * vv[j];
            }
        }
        __syncthreads();
    }

    // epilogue: divide by l, store
    #pragma unroll
    for (int i = 0; i < 4; i++) {
        int q = q0 + ty * 4 + i;
        if (q < S_TOK) {
            float inv = 1.f / lsm[ty * 4 + i];
            #pragma unroll
            for (int j = 0; j < 8; j++)
                g_o[(size_t)q * C_DIM + h * DHEAD + tx * 8 + j] = acc[i][j] * inv;
        }
    }
}

// ---------------- kernel 6: output projection + bias + residual + transpose ----------------
__global__ void __launch_bounds__(256) gemm_out_kernel(
    const float* __restrict__ Wo, const float* __restrict__ bo,
    const float* __restrict__ x, float* __restrict__ out) {
    int m0 = blockIdx.y * 128, n0 = blockIdx.x * 128;
    float acc[8][8];
    #pragma unroll
    for (int i = 0; i < 8; i++)
        #pragma unroll
        for (int j = 0; j < 8; j++) acc[i][j] = 0.f;

    gemm_core(g_o, Wo, m0, n0, acc);

    int tx = threadIdx.x & 15, ty = threadIdx.x >> 4;
    #pragma unroll
    for (int i = 0; i < 8; i++) {
        int m = m0 + ty * 8 + i;
        if (m < S_TOK) {
            #pragma unroll
            for (int j = 0; j < 8; j++) {
                int n = n0 + tx * 8 + j;
                out[(size_t)n * S_TOK + m] =
                    x[(size_t)n * S_TOK + m] + bo[n] + acc[i][j];
            }
        }
    }
}

// ---------------- launcher ----------------
extern "C" void kernel_launch(void* const* d_in, const int* in_sizes, int n_in,
                              void* d_out, int out_size) {
    const float* x  = (const float*)d_in[0];
    const float* Wq = (const float*)d_in[1];
    const float* bq = (const float*)d_in[2];
    const float* Wk = (const float*)d_in[3];
    const float* bk = (const float*)d_in[4];
    const float* Wv = (const float*)d_in[5];
    const float* bv = (const float*)d_in[6];
    const float* Wo = (const float*)d_in[7];
    const float* bo = (const float*)d_in[8];
    const float* gq = (const float*)d_in[9];
    const float* gk = (const float*)d_in[10];
    float* out = (float*)d_out;

    ln_transpose_kernel<<<S_TOK / 32, 256>>>(x);
    rope_table_kernel<<<(S_TOK * HALF + 255) / 256, 256>>>();
    gemm_qkv_kernel<<<dim3(C_DIM / 128, (S_TOK + 127) / 128, 3), 256>>>(Wq, bq, Wk, bk, Wv, bv);
    rms_rope_kernel<<<dim3(S_TOK, 2), 256>>>(gq, gk);

    const int FLASH_SMEM = (3 * 64 * QROW + 64 * SROW + 256 + 3 * 64) * (int)sizeof(float);
    cudaFuncSetAttribute(flash_kernel, cudaFuncAttributeMaxDynamicSharedMemorySize, FLASH_SMEM);
    flash_kernel<<<dim3((S_TOK + 63) / 64, NHEAD), 256, FLASH_SMEM>>>();

    gemm_out_kernel<<<dim3(C_DIM / 128, (S_TOK + 127) / 128), 256>>>(Wo, bo, x, out);
}

// round 6
// speedup vs baseline: 4.7169x; 4.7169x over previous
#include <cuda_runtime.h>
#include <math.h>
#include <stdint.h>

#define S_TOK 3872
#define C_DIM 1536
#define NHEAD 12
#define DHEAD 128
#define HALF  64
#define T_DIM 8
#define H_DIM 22
#define W_DIM 22

// ---------------- scratch (device globals; no runtime allocation) ----------------
__device__ float g_xn[S_TOK * C_DIM];
__device__ float g_q [S_TOK * C_DIM];
__device__ float g_k [S_TOK * C_DIM];
__device__ float g_v [S_TOK * C_DIM];
__device__ float g_o [S_TOK * C_DIM];
__device__ float g_cos[S_TOK * HALF];
__device__ float g_sin[S_TOK * HALF];

// ---------------- helpers ----------------
__device__ __forceinline__ uint32_t smem_u32(const void* p) {
    uint32_t a;
    asm("{ .reg .u64 t; cvta.to.shared.u64 t, %1; cvt.u32.u64 %0, t; }" : "=r"(a) : "l"(p));
    return a;
}

// m16n8k8 tf32 mma: D += A*B  (A row-major 16x8, B col-layout = [n][k] rows)
__device__ __forceinline__ void mma8(float* c, const uint32_t* a, const uint32_t* b) {
    asm volatile(
        "mma.sync.aligned.m16n8k8.row.col.f32.tf32.tf32.f32 "
        "{%0,%1,%2,%3}, {%4,%5,%6,%7}, {%8,%9}, {%0,%1,%2,%3};"
        : "+f"(c[0]), "+f"(c[1]), "+f"(c[2]), "+f"(c[3])
        : "r"(a[0]), "r"(a[1]), "r"(a[2]), "r"(a[3]), "r"(b[0]), "r"(b[1]));
}

__device__ __forceinline__ float cvt_tf32(float x) {
    uint32_t t;
    asm("cvt.rna.tf32.f32 %0, %1;" : "=r"(t) : "f"(x));
    return __uint_as_float(t);
}

// ---------------- kernel 1: layernorm + (C,S) -> (S,C) transpose ----------------
__global__ void __launch_bounds__(256) ln_transpose_kernel(const float* __restrict__ x) {
    int s0 = blockIdx.x * 32;
    int sl = threadIdx.x & 31;
    int cg = threadIdx.x >> 5;

    float sum = 0.f, sq = 0.f;
    for (int c = cg; c < C_DIM; c += 8) {
        float v = x[c * S_TOK + s0 + sl];
        sum += v; sq += v * v;
    }
    __shared__ float ssum[8][32], ssq[8][32];
    ssum[cg][sl] = sum; ssq[cg][sl] = sq;
    __syncthreads();

    __shared__ float mean_s[32], rstd_s[32];
    if (cg == 0) {
        float a = 0.f, b = 0.f;
        #pragma unroll
        for (int g = 0; g < 8; g++) { a += ssum[g][sl]; b += ssq[g][sl]; }
        float m = a / C_DIM;
        float var = b / C_DIM - m * m;
        mean_s[sl] = m;
        rstd_s[sl] = rsqrtf(var + 1e-6f);
    }
    __syncthreads();

    __shared__ float tile[32][33];
    for (int c0 = 0; c0 < C_DIM; c0 += 32) {
        #pragma unroll
        for (int r = 0; r < 4; r++) {
            int cl = cg + 8 * r;
            tile[cl][sl] = x[(c0 + cl) * S_TOK + s0 + sl];
        }
        __syncthreads();
        #pragma unroll
        for (int r = 0; r < 4; r++) {
            int srow = cg + 8 * r;
            g_xn[(s0 + srow) * C_DIM + c0 + sl] =
                (tile[sl][srow] - mean_s[srow]) * rstd_s[srow];
        }
        __syncthreads();
    }
}

// ---------------- kernel 2: RoPE cos/sin table ----------------
__global__ void rope_table_kernel() {
    int idx = blockIdx.x * blockDim.x + threadIdx.x;
    if (idx >= S_TOK * HALF) return;
    int s = idx >> 6, j = idx & 63;
    int t  = s / (H_DIM * W_DIM);
    int rem = s % (H_DIM * W_DIM);
    int hh = rem / W_DIM, ww = rem % W_DIM;
    const double LT = log(10000.0);
    double a;
    if (j < 22)      a = (double)t  * exp(-(double)j        / 22.0 * LT);
    else if (j < 43) a = (double)hh * exp(-(double)(j - 22) / 21.0 * LT);
    else             a = (double)ww * exp(-(double)(j - 43) / 21.0 * LT);
    g_cos[idx] = (float)cos(a);
    g_sin[idx] = (float)sin(a);
}

// ---------------- tf32 mma GEMM core ----------------
// D[128x128] = A[m0:,:] @ Bw[n0:,:]^T, K = C_DIM, BK = 32.
// smem per buffer: As[128][36] floats (18432B) then Bs[128][36].
#define GBK    32
#define GSTR   36
#define GBUF_F 9216          // floats per buffer (As+Bs)
#define GEMM_SMEM (2 * GBUF_F * 4)
#define NCH    (C_DIM / GBK) // 48

__device__ __forceinline__ void g_fill(uint32_t sbase, int buf,
                                       const float* __restrict__ A,
                                       const float* __restrict__ Bw,
                                       int m0, int n0, int k0) {
    int tid = threadIdx.x;
    uint32_t bb = sbase + (uint32_t)buf * (GBUF_F * 4);
    #pragma unroll
    for (int it = 0; it < 8; it++) {
        int idx = it * 256 + tid;        // 0..2047
        int row = idx >> 3;              // 0..255
        int seg = idx & 7;               // 16B segment
        int r   = row & 127;
        bool isB = row >= 128;
        uint32_t dst = bb + (isB ? 18432u : 0u) + (uint32_t)(r * (GSTR * 4) + seg * 16);
        int gr = (isB ? n0 : m0) + r;
        int sz = 16;
        if (!isB && gr >= S_TOK) { sz = 0; gr = 0; }
        const float* src = (isB ? Bw : A) + (size_t)gr * C_DIM + k0 + seg * 4;
        asm volatile("cp.async.cg.shared.global [%0], [%1], 16, %2;"
                     :: "r"(dst), "l"(src), "r"(sz));
    }
}

__device__ __forceinline__ void g_compute(const float* __restrict__ sm, int buf,
                                          int wm, int wn, int gid, int tig,
                                          float (&acc)[4][4][4]) {
    const float* As = sm + buf * GBUF_F;
    const float* Bs = As + 4608;
    #pragma unroll
    for (int ks = 0; ks < 4; ks++) {
        int kb = ks * 8;
        uint32_t af[4][4];
        #pragma unroll
        for (int mt = 0; mt < 4; mt++) {
            int m = wm * 64 + mt * 16 + gid;
            af[mt][0] = __float_as_uint(As[m * GSTR + kb + tig]);
            af[mt][1] = __float_as_uint(As[(m + 8) * GSTR + kb + tig]);
            af[mt][2] = __float_as_uint(As[m * GSTR + kb + 4 + tig]);
            af[mt][3] = __float_as_uint(As[(m + 8) * GSTR + kb + 4 + tig]);
        }
        uint32_t bf[4][2];
        #pragma unroll
        for (int nt = 0; nt < 4; nt++) {
            int n = wn * 32 + nt * 8 + gid;
            bf[nt][0] = __float_as_uint(Bs[n * GSTR + kb + tig]);
            bf[nt][1] = __float_as_uint(Bs[n * GSTR + kb + 4 + tig]);
        }
        #pragma unroll
        for (int mt = 0; mt < 4; mt++)
            #pragma unroll
            for (int nt = 0; nt < 4; nt++)
                mma8(acc[mt][nt], af[mt], bf[nt]);
    }
}

__device__ __forceinline__ void gemm_main(const float* __restrict__ A,
                                          const float* __restrict__ Bw,
                                          int m0, int n0, float* sm,
                                          float (&acc)[4][4][4]) {
    uint32_t sbase = smem_u32(sm);
    int tid = threadIdx.x;
    int wid = tid >> 5, lane = tid & 31;
    int wm = wid >> 2, wn = wid & 3;
    int gid = lane >> 2, tig = lane & 3;

    g_fill(sbase, 0, A, Bw, m0, n0, 0);
    asm volatile("cp.async.commit_group;");
    g_fill(sbase, 1, A, Bw, m0, n0, GBK);
    asm volatile("cp.async.commit_group;");

    for (int c = 0; c < NCH; c++) {
        if (c == NCH - 1) asm volatile("cp.async.wait_group 0;");
        else              asm volatile("cp.async.wait_group 1;");
        __syncthreads();
        g_compute(sm, c & 1, wm, wn, gid, tig, acc);
        __syncthreads();
        if (c + 2 < NCH) {
            g_fill(sbase, c & 1, A, Bw, m0, n0, (c + 2) * GBK);
            asm volatile("cp.async.commit_group;");
        }
    }
}

// ---------------- kernel 3: Q/K/V projections ----------------
__global__ void __launch_bounds__(256) gemm_qkv_tc(
    const float* __restrict__ Wq, const float* __restrict__ bq,
    const float* __restrict__ Wk, const float* __restrict__ bk,
    const float* __restrict__ Wv, const float* __restrict__ bv) {
    extern __shared__ float gsm[];
    const float *Wm, *bias; float* out;
    if (blockIdx.z == 0)      { Wm = Wq; bias = bq; out = g_q; }
    else if (blockIdx.z == 1) { Wm = Wk; bias = bk; out = g_k; }
    else                      { Wm = Wv; bias = bv; out = g_v; }

    int m0 = blockIdx.y * 128, n0 = blockIdx.x * 128;
    float acc[4][4][4];
    #pragma unroll
    for (int a = 0; a < 4; a++)
        #pragma unroll
        for (int b = 0; b < 4; b++)
            #pragma unroll
            for (int cc = 0; cc < 4; cc++) acc[a][b][cc] = 0.f;

    gemm_main(g_xn, Wm, m0, n0, gsm, acc);

    int wid = threadIdx.x >> 5, lane = threadIdx.x & 31;
    int wm = wid >> 2, wn = wid & 3;
    int gid = lane >> 2, tig = lane & 3;
    #pragma unroll
    for (int mt = 0; mt < 4; mt++) {
        int row = m0 + wm * 64 + mt * 16 + gid;
        #pragma unroll
        for (int nt = 0; nt < 4; nt++) {
            int col = n0 + wn * 32 + nt * 8 + tig * 2;
            float b0 = bias[col], b1 = bias[col + 1];
            if (row < S_TOK) {
                out[(size_t)row * C_DIM + col]     = acc[mt][nt][0] + b0;
                out[(size_t)row * C_DIM + col + 1] = acc[mt][nt][1] + b1;
            }
            if (row + 8 < S_TOK) {
                out[(size_t)(row + 8) * C_DIM + col]     = acc[mt][nt][2] + b0;
                out[(size_t)(row + 8) * C_DIM + col + 1] = acc[mt][nt][3] + b1;
            }
        }
    }
}

// ---------------- kernel 4: RMSNorm + RoPE, in-place ----------------
__global__ void __launch_bounds__(256) rms_rope_kernel(const float* __restrict__ gq,
                                                       const float* __restrict__ gk) {
    int s = blockIdx.x;
    float* data    = (blockIdx.y == 0) ? g_q : g_k;
    const float* g = (blockIdx.y == 0) ? gq  : gk;

    float ss = 0.f;
    for (int c = threadIdx.x; c < C_DIM; c += 256) {
        float v = data[(size_t)s * C_DIM + c];
        ss += v * v;
    }
    __shared__ float red[256];
    red[threadIdx.x] = ss;
    __syncthreads();
    for (int off = 128; off > 0; off >>= 1) {
        if (threadIdx.x < off) red[threadIdx.x] += red[threadIdx.x + off];
        __syncthreads();
    }
    float rs = rsqrtf(red[0] / C_DIM + 1e-6f);

    for (int p = threadIdx.x; p < NHEAD * HALF; p += 256) {
        int head = p >> 6, j = p & 63;
        int cr = head * DHEAD + 2 * j, ci = cr + 1;
        float xr = data[(size_t)s * C_DIM + cr] * rs * g[cr];
        float xi = data[(size_t)s * C_DIM + ci] * rs * g[ci];
        float co = g_cos[s * HALF + j], si = g_sin[s * HALF + j];
        data[(size_t)s * C_DIM + cr] = xr * co - xi * si;
        data[(size_t)s * C_DIM + ci] = xr * si + xi * co;
    }
}

// ---------------- kernel 5: flash attention (tf32 mma) ----------------
// BQ=128, BK=64, d=128. 256 threads.
#define QSTR 132
#define KSTR 136
#define SSTR 68
#define FQ_F   (128 * QSTR)   // 16896
#define FK_F   (64 * KSTR)    // 8704
#define FS_F   (128 * SSTR)   // 8704
#define FLASH_F (FQ_F + 2 * FK_F + FS_F + 128 + 128 + 128 + 256)
#define FLASH_SMEM (FLASH_F * 4)

extern __shared__ float fsm[];

__global__ void __launch_bounds__(256) flash_kernel() {
    float* Qs   = fsm;
    float* Ks   = Qs + FQ_F;
    float* Vs   = Ks + FK_F;
    float* Ssm  = Vs + FK_F;
    float* msm  = Ssm + FS_F;
    float* lsm  = msm + 128;
    float* alsm = lsm + 128;
    float* red  = alsm + 128;

    int q0 = blockIdx.x * 128;
    int h  = blockIdx.y;
    int tid = threadIdx.x;
    int wid = tid >> 5, lane = tid & 31;
    int gid = lane >> 2, tig = lane & 3;
    const float scale = 0.08838834764831845f;  // 1/sqrt(128)

    // load Q tile [128][128]
    #pragma unroll
    for (int it = 0; it < 16; it++) {
        int i4 = it * 256 + tid;          // float4 index
        int row = i4 >> 5;
        int c4 = (i4 & 31) << 2;
        float4 v = (q0 + row < S_TOK)
            ? *(const float4*)&g_q[(size_t)(q0 + row) * C_DIM + h * DHEAD + c4]
            : make_float4(0.f, 0.f, 0.f, 0.f);
        *(float4*)&Qs[row * QSTR + c4] = v;
    }
    if (tid < 128) { msm[tid] = -1e30f; lsm[tid] = 0.f; alsm[tid] = 0.f; }

    // PV accumulators (persistent): warp grid 2(m) x 4(n), warp tile 64x32
    int wmP = wid >> 2, wnP = wid & 3;
    float oacc[4][4][4];
    #pragma unroll
    for (int a = 0; a < 4; a++)
        #pragma unroll
        for (int b = 0; b < 4; b++)
            #pragma unroll
            for (int cc = 0; cc < 4; cc++) oacc[a][b][cc] = 0.f;

    // S warp grid: 4(m) x 2(n), warp tile 32x32
    int wmS = wid >> 1, wnS = wid & 1;

    int row2 = tid >> 1, part = tid & 1;   // softmax: 2 threads/row

    for (int k0 = 0; k0 < S_TOK; k0 += 64) {
        __syncthreads();  // prev PV done with Ks/Vs
        // load K,V tiles [64][128]
        #pragma unroll
        for (int it = 0; it < 8; it++) {
            int i4 = it * 256 + tid;
            int row = i4 >> 5;
            int c4 = (i4 & 31) << 2;
            bool ok = (k0 + row < S_TOK);
            float4 kv = ok
                ? *(const float4*)&g_k[(size_t)(k0 + row) * C_DIM + h * DHEAD + c4]
                : make_float4(0.f, 0.f, 0.f, 0.f);
            float4 vv = ok
                ? *(const float4*)&g_v[(size_t)(k0 + row) * C_DIM + h * DHEAD + c4]
                : make_float4(0.f, 0.f, 0.f, 0.f);
            *(float4*)&Ks[row * KSTR + c4] = kv;
            *(float4*)&Vs[row * KSTR + c4] = vv;
        }
        __syncthreads();

        // ---- S = Q @ K^T : [128][64] ----
        float sacc[2][4][4];
        #pragma unroll
        for (int a = 0; a < 2; a++)
            #pragma unroll
            for (int b = 0; b < 4; b++)
                #pragma unroll
                for (int cc = 0; cc < 4; cc++) sacc[a][b][cc] = 0.f;

        #pragma unroll
        for (int ks = 0; ks < 16; ks++) {
            int kb = ks * 8;
            uint32_t af[2][4];
            #pragma unroll
            for (int mt = 0; mt < 2; mt++) {
                int m = wmS * 32 + mt * 16 + gid;
                af[mt][0] = __float_as_uint(Qs[m * QSTR + kb + tig]);
                af[mt][1] = __float_as_uint(Qs[(m + 8) * QSTR + kb + tig]);
                af[mt][2] = __float_as_uint(Qs[m * QSTR + kb + 4 + tig]);
                af[mt][3] = __float_as_uint(Qs[(m + 8) * QSTR + kb + 4 + tig]);
            }
            uint32_t bf[4][2];
            #pragma unroll
            for (int nt = 0; nt < 4; nt++) {
                int n = wnS * 32 + nt * 8 + gid;
                bf[nt][0] = __float_as_uint(Ks[n * KSTR + kb + tig]);
                bf[nt][1] = __float_as_uint(Ks[n * KSTR + kb + 4 + tig]);
            }
            #pragma unroll
            for (int mt = 0; mt < 2; mt++)
                #pragma unroll
                for (int nt = 0; nt < 4; nt++)
                    mma8(sacc[mt][nt], af[mt], bf[nt]);
        }
        // write S to smem with scale + mask
        #pragma unroll
        for (int mt = 0; mt < 2; mt++) {
            int row = wmS * 32 + mt * 16 + gid;
            #pragma unroll
            for (int nt = 0; nt < 4; nt++) {
                int col = wnS * 32 + nt * 8 + tig * 2;
                int kg = k0 + col;
                Ssm[row * SSTR + col]           = (kg < S_TOK)     ? sacc[mt][nt][0] * scale : -1e30f;
                Ssm[row * SSTR + col + 1]       = (kg + 1 < S_TOK) ? sacc[mt][nt][1] * scale : -1e30f;
                Ssm[(row + 8) * SSTR + col]     = (kg < S_TOK)     ? sacc[mt][nt][2] * scale : -1e30f;
                Ssm[(row + 8) * SSTR + col + 1] = (kg + 1 < S_TOK) ? sacc[mt][nt][3] * scale : -1e30f;
            }
        }
        __syncthreads();

        // ---- online softmax (2 threads per row, 32 keys each) ----
        float mx = -1e30f;
        #pragma unroll
        for (int u = 0; u < 32; u++)
            mx = fmaxf(mx, Ssm[row2 * SSTR + part * 32 + u]);
        red[row2 * 2 + part] = mx;
        __syncthreads();
        if (part == 0) {
            float m_old = msm[row2];
            float mn = fmaxf(m_old, fmaxf(red[row2 * 2], red[row2 * 2 + 1]));
            alsm[row2] = __expf(m_old - mn);
            msm[row2] = mn;
        }
        __syncthreads();
        float mrow = msm[row2];
        float psum = 0.f;
        #pragma unroll
        for (int u = 0; u < 32; u++) {
            float pv = __expf(Ssm[row2 * SSTR + part * 32 + u] - mrow);
            psum += pv;
            Ssm[row2 * SSTR + part * 32 + u] = cvt_tf32(pv);
        }
        red[row2 * 2 + part] = psum;
        __syncthreads();
        if (part == 0)
            lsm[row2] = lsm[row2] * alsm[row2] + red[row2 * 2] + red[row2 * 2 + 1];

        // ---- PV: O[128][128] += P[128][64] @ V[64][128] ----
        #pragma unroll
        for (int mt = 0; mt < 4; mt++) {
            int r = wmP * 64 + mt * 16 + gid;
            float al0 = alsm[r], al1 = alsm[r + 8];
            #pragma unroll
            for (int nt = 0; nt < 4; nt++) {
                oacc[mt][nt][0] *= al0; oacc[mt][nt][1] *= al0;
                oacc[mt][nt][2] *= al1; oacc[mt][nt][3] *= al1;
            }
        }
        #pragma unroll
        for (int ks = 0; ks < 8; ks++) {
            int kb = ks * 8;
            uint32_t af[4][4];
            #pragma unroll
            for (int mt = 0; mt < 4; mt++) {
                int m = wmP * 64 + mt * 16 + gid;
                af[mt][0] = __float_as_uint(Ssm[m * SSTR + kb + tig]);
                af[mt][1] = __float_as_uint(Ssm[(m + 8) * SSTR + kb + tig]);
                af[mt][2] = __float_as_uint(Ssm[m * SSTR + kb + 4 + tig]);
                af[mt][3] = __float_as_uint(Ssm[(m + 8) * SSTR + kb + 4 + tig]);
            }
            uint32_t bf[4][2];
            #pragma unroll
            for (int nt = 0; nt < 4; nt++) {
                int n = wnP * 32 + nt * 8 + gid;
                bf[nt][0] = __float_as_uint(Vs[(kb + tig) * KSTR + n]);
                bf[nt][1] = __float_as_uint(Vs[(kb + 4 + tig) * KSTR + n]);
            }
            #pragma unroll
            for (int mt = 0; mt < 4; mt++)
                #pragma unroll
                for (int nt = 0; nt < 4; nt++)
                    mma8(oacc[mt][nt], af[mt], bf[nt]);
        }
    }
    __syncthreads();  // lsm updates visible

    // epilogue
    #pragma unroll
    for (int mt = 0; mt < 4; mt++) {
        int r = wmP * 64 + mt * 16 + gid;
        float inv0 = 1.f / lsm[r];
        float inv1 = 1.f / lsm[r + 8];
        int gr0 = q0 + r;
        #pragma unroll
        for (int nt = 0; nt < 4; nt++) {
            int col = h * DHEAD + wnP * 32 + nt * 8 + tig * 2;
            if (gr0 < S_TOK) {
                g_o[(size_t)gr0 * C_DIM + col]     = oacc[mt][nt][0] * inv0;
                g_o[(size_t)gr0 * C_DIM + col + 1] = oacc[mt][nt][1] * inv0;
            }
            if (gr0 + 8 < S_TOK) {
                g_o[(size_t)(gr0 + 8) * C_DIM + col]     = oacc[mt][nt][2] * inv1;
                g_o[(size_t)(gr0 + 8) * C_DIM + col + 1] = oacc[mt][nt][3] * inv1;
            }
        }
    }
}

// ---------------- kernel 6: output projection + residual + transpose ----------------
__global__ void __launch_bounds__(256) gemm_out_tc(
    const float* __restrict__ Wo, const float* __restrict__ bo,
    const float* __restrict__ x, float* __restrict__ outp) {
    extern __shared__ float gsm[];
    int m0 = blockIdx.y * 128, n0 = blockIdx.x * 128;
    float acc[4][4][4];
    #pragma unroll
    for (int a = 0; a < 4; a++)
        #pragma unroll
        for (int b = 0; b < 4; b++)
            #pragma unroll
            for (int cc = 0; cc < 4; cc++) acc[a][b][cc] = 0.f;

    gemm_main(g_o, Wo, m0, n0, gsm, acc);

    int wid = threadIdx.x >> 5, lane = threadIdx.x & 31;
    int wm = wid >> 2, wn = wid & 3;
    int gid = lane >> 2, tig = lane & 3;
    #pragma unroll
    for (int mt = 0; mt < 4; mt++) {
        int row = m0 + wm * 64 + mt * 16 + gid;
        #pragma unroll
        for (int nt = 0; nt < 4; nt++) {
            int col = n0 + wn * 32 + nt * 8 + tig * 2;
            float b0 = bo[col], b1 = bo[col + 1];
            if (row < S_TOK) {
                size_t i0 = (size_t)col * S_TOK + row;
                size_t i1 = (size_t)(col + 1) * S_TOK + row;
                outp[i0] = x[i0] + b0 + acc[mt][nt][0];
                outp[i1] = x[i1] + b1 + acc[mt][nt][1];
            }
            if (row + 8 < S_TOK) {
                size_t i2 = (size_t)col * S_TOK + row + 8;
                size_t i3 = (size_t)(col + 1) * S_TOK + row + 8;
                outp[i2] = x[i2] + b0 + acc[mt][nt][2];
                outp[i3] = x[i3] + b1 + acc[mt][nt][3];
            }
        }
    }
}

// ---------------- launcher ----------------
extern "C" void kernel_launch(void* const* d_in, const int* in_sizes, int n_in,
                              void* d_out, int out_size) {
    const float* x  = (const float*)d_in[0];
    const float* Wq = (const float*)d_in[1];
    const float* bq = (const float*)d_in[2];
    const float* Wk = (const float*)d_in[3];
    const float* bk = (const float*)d_in[4];
    const float* Wv = (const float*)d_in[5];
    const float* bv = (const float*)d_in[6];
    const float* Wo = (const float*)d_in[7];
    const float* bo = (const float*)d_in[8];
    const float* gq = (const float*)d_in[9];
    const float* gk = (const float*)d_in[10];
    float* out = (float*)d_out;

    ln_transpose_kernel<<<S_TOK / 32, 256>>>(x);
    rope_table_kernel<<<(S_TOK * HALF + 255) / 256, 256>>>();

    cudaFuncSetAttribute(gemm_qkv_tc, cudaFuncAttributeMaxDynamicSharedMemorySize, GEMM_SMEM);
    cudaFuncSetAttribute(gemm_out_tc, cudaFuncAttributeMaxDynamicSharedMemorySize, GEMM_SMEM);
    cudaFuncSetAttribute(flash_kernel, cudaFuncAttributeMaxDynamicSharedMemorySize, FLASH_SMEM);

    gemm_qkv_tc<<<dim3(C_DIM / 128, (S_TOK + 127) / 128, 3), 256, GEMM_SMEM>>>(
        Wq, bq, Wk, bk, Wv, bv);
    rms_rope_kernel<<<dim3(S_TOK, 2), 256>>>(gq, gk);

    flash_kernel<<<dim3((S_TOK + 127) / 128, NHEAD), 256, FLASH_SMEM>>>();

    gemm_out_tc<<<dim3(C_DIM / 128, (S_TOK + 127) / 128), 256, GEMM_SMEM>>>(Wo, bo, x, out);
}

// round 7
// speedup vs baseline: 5.1098x; 1.0833x over previous
#include <cuda_runtime.h>
#include <math.h>
#include <stdint.h>

#define S_TOK 3872
#define C_DIM 1536
#define NHEAD 12
#define DHEAD 128
#define HALF  64
#define T_DIM 8
#define H_DIM 22
#define W_DIM 22

// ---------------- scratch (device globals; no runtime allocation) ----------------
__device__ float g_xn[S_TOK * C_DIM];
__device__ float g_q [S_TOK * C_DIM];
__device__ float g_k [S_TOK * C_DIM];
__device__ float g_v [S_TOK * C_DIM];
__device__ float g_o [S_TOK * C_DIM];
__device__ float g_cos[S_TOK * HALF];
__device__ float g_sin[S_TOK * HALF];

// ---------------- helpers ----------------
__device__ __forceinline__ uint32_t smem_u32(const void* p) {
    uint32_t a;
    asm("{ .reg .u64 t; cvta.to.shared.u64 t, %1; cvt.u32.u64 %0, t; }" : "=r"(a) : "l"(p));
    return a;
}

// m16n8k8 tf32 mma: D += A*B  (A row-major 16x8, B col-layout = [n][k] rows)
__device__ __forceinline__ void mma8(float* c, const uint32_t* a, const uint32_t* b) {
    asm volatile(
        "mma.sync.aligned.m16n8k8.row.col.f32.tf32.tf32.f32 "
        "{%0,%1,%2,%3}, {%4,%5,%6,%7}, {%8,%9}, {%0,%1,%2,%3};"
        : "+f"(c[0]), "+f"(c[1]), "+f"(c[2]), "+f"(c[3])
        : "r"(a[0]), "r"(a[1]), "r"(a[2]), "r"(a[3]), "r"(b[0]), "r"(b[1]));
}

__device__ __forceinline__ float cvt_tf32(float x) {
    uint32_t t;
    asm("cvt.rna.tf32.f32 %0, %1;" : "=r"(t) : "f"(x));
    return __uint_as_float(t);
}

// ---------------- kernel 1: layernorm + (C,S) -> (S,C) transpose ----------------
__global__ void __launch_bounds__(256) ln_transpose_kernel(const float* __restrict__ x) {
    int s0 = blockIdx.x * 32;
    int sl = threadIdx.x & 31;
    int cg = threadIdx.x >> 5;

    float sum = 0.f, sq = 0.f;
    for (int c = cg; c < C_DIM; c += 8) {
        float v = x[c * S_TOK + s0 + sl];
        sum += v; sq += v * v;
    }
    __shared__ float ssum[8][32], ssq[8][32];
    ssum[cg][sl] = sum; ssq[cg][sl] = sq;
    __syncthreads();

    __shared__ float mean_s[32], rstd_s[32];
    if (cg == 0) {
        float a = 0.f, b = 0.f;
        #pragma unroll
        for (int g = 0; g < 8; g++) { a += ssum[g][sl]; b += ssq[g][sl]; }
        float m = a / C_DIM;
        float var = b / C_DIM - m * m;
        mean_s[sl] = m;
        rstd_s[sl] = rsqrtf(var + 1e-6f);
    }
    __syncthreads();

    __shared__ float tile[32][33];
    for (int c0 = 0; c0 < C_DIM; c0 += 32) {
        #pragma unroll
        for (int r = 0; r < 4; r++) {
            int cl = cg + 8 * r;
            tile[cl][sl] = x[(c0 + cl) * S_TOK + s0 + sl];
        }
        __syncthreads();
        #pragma unroll
        for (int r = 0; r < 4; r++) {
            int srow = cg + 8 * r;
            g_xn[(s0 + srow) * C_DIM + c0 + sl] =
                (tile[sl][srow] - mean_s[srow]) * rstd_s[srow];
        }
        __syncthreads();
    }
}

// ---------------- kernel 2: RoPE cos/sin table ----------------
__global__ void rope_table_kernel() {
    int idx = blockIdx.x * blockDim.x + threadIdx.x;
    if (idx >= S_TOK * HALF) return;
    int s = idx >> 6, j = idx & 63;
    int t  = s / (H_DIM * W_DIM);
    int rem = s % (H_DIM * W_DIM);
    int hh = rem / W_DIM, ww = rem % W_DIM;
    const double LT = log(10000.0);
    double a;
    if (j < 22)      a = (double)t  * exp(-(double)j        / 22.0 * LT);
    else if (j < 43) a = (double)hh * exp(-(double)(j - 22) / 21.0 * LT);
    else             a = (double)ww * exp(-(double)(j - 43) / 21.0 * LT);
    g_cos[idx] = (float)cos(a);
    g_sin[idx] = (float)sin(a);
}

// ---------------- tf32 mma GEMM core ----------------
#define GBK    32
#define GSTR   36
#define GBUF_F 9216
#define GEMM_SMEM (2 * GBUF_F * 4)
#define NCH    (C_DIM / GBK)

__device__ __forceinline__ void g_fill(uint32_t sbase, int buf,
                                       const float* __restrict__ A,
                                       const float* __restrict__ Bw,
                                       int m0, int n0, int k0) {
    int tid = threadIdx.x;
    uint32_t bb = sbase + (uint32_t)buf * (GBUF_F * 4);
    #pragma unroll
    for (int it = 0; it < 8; it++) {
        int idx = it * 256 + tid;
        int row = idx >> 3;
        int seg = idx & 7;
        int r   = row & 127;
        bool isB = row >= 128;
        uint32_t dst = bb + (isB ? 18432u : 0u) + (uint32_t)(r * (GSTR * 4) + seg * 16);
        int gr = (isB ? n0 : m0) + r;
        int sz = 16;
        if (!isB && gr >= S_TOK) { sz = 0; gr = 0; }
        const float* src = (isB ? Bw : A) + (size_t)gr * C_DIM + k0 + seg * 4;
        asm volatile("cp.async.cg.shared.global [%0], [%1], 16, %2;"
                     :: "r"(dst), "l"(src), "r"(sz));
    }
}

__device__ __forceinline__ void g_compute(const float* __restrict__ sm, int buf,
                                          int wm, int wn, int gid, int tig,
                                          float (&acc)[4][4][4]) {
    const float* As = sm + buf * GBUF_F;
    const float* Bs = As + 4608;
    #pragma unroll
    for (int ks = 0; ks < 4; ks++) {
        int kb = ks * 8;
        uint32_t af[4][4];
        #pragma unroll
        for (int mt = 0; mt < 4; mt++) {
            int m = wm * 64 + mt * 16 + gid;
            af[mt][0] = __float_as_uint(As[m * GSTR + kb + tig]);
            af[mt][1] = __float_as_uint(As[(m + 8) * GSTR + kb + tig]);
            af[mt][2] = __float_as_uint(As[m * GSTR + kb + 4 + tig]);
            af[mt][3] = __float_as_uint(As[(m + 8) * GSTR + kb + 4 + tig]);
        }
        uint32_t bf[4][2];
        #pragma unroll
        for (int nt = 0; nt < 4; nt++) {
            int n = wn * 32 + nt * 8 + gid;
            bf[nt][0] = __float_as_uint(Bs[n * GSTR + kb + tig]);
            bf[nt][1] = __float_as_uint(Bs[n * GSTR + kb + 4 + tig]);
        }
        #pragma unroll
        for (int mt = 0; mt < 4; mt++)
            #pragma unroll
            for (int nt = 0; nt < 4; nt++)
                mma8(acc[mt][nt], af[mt], bf[nt]);
    }
}

__device__ __forceinline__ void gemm_main(const float* __restrict__ A,
                                          const float* __restrict__ Bw,
                                          int m0, int n0, float* sm,
                                          float (&acc)[4][4][4]) {
    uint32_t sbase = smem_u32(sm);
    int tid = threadIdx.x;
    int wid = tid >> 5, lane = tid & 31;
    int wm = wid >> 2, wn = wid & 3;
    int gid = lane >> 2, tig = lane & 3;

    g_fill(sbase, 0, A, Bw, m0, n0, 0);
    asm volatile("cp.async.commit_group;");
    g_fill(sbase, 1, A, Bw, m0, n0, GBK);
    asm volatile("cp.async.commit_group;");

    for (int c = 0; c < NCH; c++) {
        if (c == NCH - 1) asm volatile("cp.async.wait_group 0;");
        else              asm volatile("cp.async.wait_group 1;");
        __syncthreads();
        g_compute(sm, c & 1, wm, wn, gid, tig, acc);
        __syncthreads();
        if (c + 2 < NCH) {
            g_fill(sbase, c & 1, A, Bw, m0, n0, (c + 2) * GBK);
            asm volatile("cp.async.commit_group;");
        }
    }
}

// ---------------- kernel 3: Q/K/V projections ----------------
__global__ void __launch_bounds__(256, 2) gemm_qkv_tc(
    const float* __restrict__ Wq, const float* __restrict__ bq,
    const float* __restrict__ Wk, const float* __restrict__ bk,
    const float* __restrict__ Wv, const float* __restrict__ bv) {
    extern __shared__ float gsm[];
    const float *Wm, *bias; float* out;
    if (blockIdx.z == 0)      { Wm = Wq; bias = bq; out = g_q; }
    else if (blockIdx.z == 1) { Wm = Wk; bias = bk; out = g_k; }
    else                      { Wm = Wv; bias = bv; out = g_v; }

    int m0 = blockIdx.y * 128, n0 = blockIdx.x * 128;
    float acc[4][4][4];
    #pragma unroll
    for (int a = 0; a < 4; a++)
        #pragma unroll
        for (int b = 0; b < 4; b++)
            #pragma unroll
            for (int cc = 0; cc < 4; cc++) acc[a][b][cc] = 0.f;

    gemm_main(g_xn, Wm, m0, n0, gsm, acc);

    int wid = threadIdx.x >> 5, lane = threadIdx.x & 31;
    int wm = wid >> 2, wn = wid & 3;
    int gid = lane >> 2, tig = lane & 3;
    #pragma unroll
    for (int mt = 0; mt < 4; mt++) {
        int row = m0 + wm * 64 + mt * 16 + gid;
        #pragma unroll
        for (int nt = 0; nt < 4; nt++) {
            int col = n0 + wn * 32 + nt * 8 + tig * 2;
            float b0 = bias[col], b1 = bias[col + 1];
            if (row < S_TOK) {
                out[(size_t)row * C_DIM + col]     = acc[mt][nt][0] + b0;
                out[(size_t)row * C_DIM + col + 1] = acc[mt][nt][1] + b1;
            }
            if (row + 8 < S_TOK) {
                out[(size_t)(row + 8) * C_DIM + col]     = acc[mt][nt][2] + b0;
                out[(size_t)(row + 8) * C_DIM + col + 1] = acc[mt][nt][3] + b1;
            }
        }
    }
}

// ---------------- kernel 4: RMSNorm + RoPE, in-place ----------------
__global__ void __launch_bounds__(256) rms_rope_kernel(const float* __restrict__ gq,
                                                       const float* __restrict__ gk) {
    int s = blockIdx.x;
    float* data    = (blockIdx.y == 0) ? g_q : g_k;
    const float* g = (blockIdx.y == 0) ? gq  : gk;

    float ss = 0.f;
    for (int c = threadIdx.x; c < C_DIM; c += 256) {
        float v = data[(size_t)s * C_DIM + c];
        ss += v * v;
    }
    __shared__ float red[256];
    red[threadIdx.x] = ss;
    __syncthreads();
    for (int off = 128; off > 0; off >>= 1) {
        if (threadIdx.x < off) red[threadIdx.x] += red[threadIdx.x + off];
        __syncthreads();
    }
    float rs = rsqrtf(red[0] / C_DIM + 1e-6f);

    for (int p = threadIdx.x; p < NHEAD * HALF; p += 256) {
        int head = p >> 6, j = p & 63;
        int cr = head * DHEAD + 2 * j, ci = cr + 1;
        float xr = data[(size_t)s * C_DIM + cr] * rs * g[cr];
        float xi = data[(size_t)s * C_DIM + ci] * rs * g[ci];
        float co = g_cos[s * HALF + j], si = g_sin[s * HALF + j];
        data[(size_t)s * C_DIM + cr] = xr * co - xi * si;
        data[(size_t)s * C_DIM + ci] = xr * si + xi * co;
    }
}

// ---------------- kernel 5: flash attention (tf32 mma, cp.async pipelined) ----------------
// BQ=128, BK=32 (3872 % 32 == 0 -> no key masking). 256 threads, 8 warps.
#define FBK   32
#define FNIT  (S_TOK / FBK)       // 121
#define QSTR  132
#define KSTRK 132                 // K tile stride (4 mod 32 -> conflict-free n-major frags)
#define KSTRV 136                 // V tile stride (8 mod 32 -> conflict-free k-major frags)
#define PSTR  36
#define FQ_F  (128 * QSTR)        // 16896
#define FK_F  (FBK * KSTRK)       // 4224
#define FV_F  (FBK * KSTRV)       // 4352
#define FP_F  (128 * PSTR)        // 4608
#define FLASH_F (FQ_F + 2 * FK_F + 2 * FV_F + 2 * FP_F + 256)
#define FLASH_SMEM (FLASH_F * 4)

extern __shared__ float fsm[];

__device__ __forceinline__ void f_fill(uint32_t dstbase, int stride,
                                       const float* __restrict__ src, int kc, int h) {
    int tid = threadIdx.x;
    #pragma unroll
    for (int it = 0; it < 4; it++) {
        int idx = it * 256 + tid;            // 0..1023 float4s
        int row = idx >> 5, seg = idx & 31;
        uint32_t dst = dstbase + (uint32_t)(row * stride + seg * 4) * 4u;
        const float* s = src + (size_t)(kc * FBK + row) * C_DIM + h * DHEAD + seg * 4;
        asm volatile("cp.async.cg.shared.global [%0], [%1], 16;" :: "r"(dst), "l"(s));
    }
}

__global__ void __launch_bounds__(256) flash_kernel() {
    float* Qs   = fsm;
    float* Ks   = Qs + FQ_F;       // 2 buffers
    float* Vs   = Ks + 2 * FK_F;   // 2 buffers
    float* Ps   = Vs + 2 * FV_F;   // 2 buffers (S then P in place)
    float* alsm = Ps + 2 * FP_F;   // 128
    float* lsm  = alsm + 128;      // 128

    uint32_t sb = smem_u32(fsm);
    uint32_t ks_base = sb + FQ_F * 4;
    uint32_t vs_base = sb + (FQ_F + 2 * FK_F) * 4;

    int q0 = blockIdx.x * 128;
    int h  = blockIdx.y;
    int tid = threadIdx.x;
    int wid = tid >> 5, lane = tid & 31;
    int gid = lane >> 2, tig = lane & 3;
    const float scale = 0.08838834764831845f;  // 1/sqrt(128)

    // load Q tile [128][128], pre-scaled
    #pragma unroll
    for (int it = 0; it < 16; it++) {
        int i4 = it * 256 + tid;
        int row = i4 >> 5;
        int c4 = (i4 & 31) << 2;
        float4 v = (q0 + row < S_TOK)
            ? *(const float4*)&g_q[(size_t)(q0 + row) * C_DIM + h * DHEAD + c4]
            : make_float4(0.f, 0.f, 0.f, 0.f);
        v.x *= scale; v.y *= scale; v.z *= scale; v.w *= scale;
        *(float4*)&Qs[row * QSTR + c4] = v;
    }

    // prologue: K0,V0 (group) ; K1 (group)
    f_fill(ks_base, KSTRK, g_k, 0, h);
    f_fill(vs_base, KSTRV, g_v, 0, h);
    asm volatile("cp.async.commit_group;");
    f_fill(ks_base + FK_F * 4, KSTRK, g_k, 1, h);
    asm volatile("cp.async.commit_group;");

    // per-thread softmax state: thread owns half of row (tid>>1)
    int row2 = tid >> 1, part = tid & 1;
    float m_reg = -1e30f, l_reg = 0.f;

    // PV accumulators: warps 2(m) x 4(n), warp tile 64x32
    int wmP = wid >> 2, wnP = wid & 3;
    float oacc[4][4][4];
    #pragma unroll
    for (int a = 0; a < 4; a++)
        #pragma unroll
        for (int b = 0; b < 4; b++)
            #pragma unroll
            for (int cc = 0; cc < 4; cc++) oacc[a][b][cc] = 0.f;

    // S warp grid: 4(m) x 2(n), warp tile 32x16
    int wmS = wid >> 1, wnS = wid & 1;

    asm volatile("cp.async.wait_group 1;");   // K0,V0 ready
    __syncthreads();

    for (int c = 0; c < FNIT; c++) {
        const float* Kb = Ks + (c & 1) * FK_F;
        const float* Vb = Vs + (c & 1) * FV_F;
        float* Sb = Ps + (c & 1) * FP_F;

        // ---- S = Q @ K^T : [128][32] ----
        float sacc[2][2][4];
        #pragma unroll
        for (int a = 0; a < 2; a++)
            #pragma unroll
            for (int b = 0; b < 2; b++)
                #pragma unroll
                for (int cc = 0; cc < 4; cc++) sacc[a][b][cc] = 0.f;

        #pragma unroll
        for (int ks = 0; ks < 16; ks++) {
            int kb = ks * 8;
            uint32_t af[2][4];
            #pragma unroll
            for (int mt = 0; mt < 2; mt++) {
                int m = wmS * 32 + mt * 16 + gid;
                af[mt][0] = __float_as_uint(Qs[m * QSTR + kb + tig]);
                af[mt][1] = __float_as_uint(Qs[(m + 8) * QSTR + kb + tig]);
                af[mt][2] = __float_as_uint(Qs[m * QSTR + kb + 4 + tig]);
                af[mt][3] = __float_as_uint(Qs[(m + 8) * QSTR + kb + 4 + tig]);
            }
            uint32_t bf[2][2];
            #pragma unroll
            for (int nt = 0; nt < 2; nt++) {
                int n = wnS * 16 + nt * 8 + gid;
                bf[nt][0] = __float_as_uint(Kb[n * KSTRK + kb + tig]);
                bf[nt][1] = __float_as_uint(Kb[n * KSTRK + kb + 4 + tig]);
            }
            #pragma unroll
            for (int mt = 0; mt < 2; mt++)
                #pragma unroll
                for (int nt = 0; nt < 2; nt++)
                    mma8(sacc[mt][nt], af[mt], bf[nt]);
        }
        #pragma unroll
        for (int mt = 0; mt < 2; mt++) {
            int row = wmS * 32 + mt * 16 + gid;
            #pragma unroll
            for (int nt = 0; nt < 2; nt++) {
                int col = wnS * 16 + nt * 8 + tig * 2;
                Sb[row * PSTR + col]           = sacc[mt][nt][0];
                Sb[row * PSTR + col + 1]       = sacc[mt][nt][1];
                Sb[(row + 8) * PSTR + col]     = sacc[mt][nt][2];
                Sb[(row + 8) * PSTR + col + 1] = sacc[mt][nt][3];
            }
        }
        __syncthreads();   // S visible; all warps done S-mma(c) & PV(c-1)

        // issue fills for K(c+2), V(c+1); always commit (uniform group count)
        if (c + 2 < FNIT) f_fill(ks_base + (c & 1) * FK_F * 4, KSTRK, g_k, c + 2, h);
        if (c + 1 < FNIT) f_fill(vs_base + ((c + 1) & 1) * FV_F * 4, KSTRV, g_v, c + 1, h);
        asm volatile("cp.async.commit_group;");

        // ---- softmax: thread owns 16 cols of its row ----
        {
            float* p0 = &Sb[row2 * PSTR + part * 16];
            float4 v0 = *(float4*)&p0[0], v1 = *(float4*)&p0[4];
            float4 v2 = *(float4*)&p0[8], v3 = *(float4*)&p0[12];
            float mx = fmaxf(fmaxf(fmaxf(v0.x, v0.y), fmaxf(v0.z, v0.w)),
                             fmaxf(fmaxf(v1.x, v1.y), fmaxf(v1.z, v1.w)));
            mx = fmaxf(mx, fmaxf(fmaxf(fmaxf(v2.x, v2.y), fmaxf(v2.z, v2.w)),
                                 fmaxf(fmaxf(v3.x, v3.y), fmaxf(v3.z, v3.w))));
            mx = fmaxf(mx, __shfl_xor_sync(0xFFFFFFFFu, mx, 1));
            float mnew = fmaxf(m_reg, mx);
            float alpha = __expf(m_reg - mnew);
            m_reg = mnew;

            float ps = 0.f;
            float4 e0, e1, e2, e3;
            e0.x = __expf(v0.x - mnew); e0.y = __expf(v0.y - mnew);
            e0.z = __expf(v0.z - mnew); e0.w = __expf(v0.w - mnew);
            e1.x = __expf(v1.x - mnew); e1.y = __expf(v1.y - mnew);
            e1.z = __expf(v1.z - mnew); e1.w = __expf(v1.w - mnew);
            e2.x = __expf(v2.x - mnew); e2.y = __expf(v2.y - mnew);
            e2.z = __expf(v2.z - mnew); e2.w = __expf(v2.w - mnew);
            e3.x = __expf(v3.x - mnew); e3.y = __expf(v3.y - mnew);
            e3.z = __expf(v3.z - mnew); e3.w = __expf(v3.w - mnew);
            ps = (e0.x + e0.y + e0.z + e0.w) + (e1.x + e1.y + e1.z + e1.w)
               + (e2.x + e2.y + e2.z + e2.w) + (e3.x + e3.y + e3.z + e3.w);
            // round P to tf32 (rna) for PV mma
            e0.x = cvt_tf32(e0.x); e0.y = cvt_tf32(e0.y); e0.z = cvt_tf32(e0.z); e0.w = cvt_tf32(e0.w);
            e1.x = cvt_tf32(e1.x); e1.y = cvt_tf32(e1.y); e1.z = cvt_tf32(e1.z); e1.w = cvt_tf32(e1.w);
            e2.x = cvt_tf32(e2.x); e2.y = cvt_tf32(e2.y); e2.z = cvt_tf32(e2.z); e2.w = cvt_tf32(e2.w);
            e3.x = cvt_tf32(e3.x); e3.y = cvt_tf32(e3.y); e3.z = cvt_tf32(e3.z); e3.w = cvt_tf32(e3.w);
            *(float4*)&p0[0] = e0; *(float4*)&p0[4] = e1;
            *(float4*)&p0[8] = e2; *(float4*)&p0[12] = e3;

            ps += __shfl_xor_sync(0xFFFFFFFFu, ps, 1);
            l_reg = l_reg * alpha + ps;
            if (part == 0) alsm[row2] = alpha;
        }

        asm volatile("cp.async.wait_group 1;");  // V(c), K(c+1) guaranteed landed
        __syncthreads();   // P + alsm visible

        // ---- PV: O[128][128] += P[128][32] @ V[32][128] ----
        #pragma unroll
        for (int mt = 0; mt < 4; mt++) {
            int r = wmP * 64 + mt * 16 + gid;
            float al0 = alsm[r], al1 = alsm[r + 8];
            #pragma unroll
            for (int nt = 0; nt < 4; nt++) {
                oacc[mt][nt][0] *= al0; oacc[mt][nt][1] *= al0;
                oacc[mt][nt][2] *= al1; oacc[mt][nt][3] *= al1;
            }
        }
        #pragma unroll
        for (int ks = 0; ks < 4; ks++) {
            int kb = ks * 8;
            uint32_t af[4][4];
            #pragma unroll
            for (int mt = 0; mt < 4; mt++) {
                int m = wmP * 64 + mt * 16 + gid;
                af[mt][0] = __float_as_uint(Sb[m * PSTR + kb + tig]);
                af[mt][1] = __float_as_uint(Sb[(m + 8) * PSTR + kb + tig]);
                af[mt][2] = __float_as_uint(Sb[m * PSTR + kb + 4 + tig]);
                af[mt][3] = __float_as_uint(Sb[(m + 8) * PSTR + kb + 4 + tig]);
            }
            uint32_t bf[4][2];
            #pragma unroll
            for (int nt = 0; nt < 4; nt++) {
                int n = wnP * 32 + nt * 8 + gid;
                bf[nt][0] = __float_as_uint(Vb[(kb + tig) * KSTRV + n]);
                bf[nt][1] = __float_as_uint(Vb[(kb + 4 + tig) * KSTRV + n]);
            }
            #pragma unroll
            for (int mt = 0; mt < 4; mt++)
                #pragma unroll
                for (int nt = 0; nt < 4; nt++)
                    mma8(oacc[mt][nt], af[mt], bf[nt]);
        }
    }

    if (part == 0) lsm[row2] = l_reg;
    __syncthreads();

    // epilogue
    #pragma unroll
    for (int mt = 0; mt < 4; mt++) {
        int r = wmP * 64 + mt * 16 + gid;
        float inv0 = 1.f / lsm[r];
        float inv1 = 1.f / lsm[r + 8];
        int gr0 = q0 + r;
        #pragma unroll
        for (int nt = 0; nt < 4; nt++) {
            int col = h * DHEAD + wnP * 32 + nt * 8 + tig * 2;
            if (gr0 < S_TOK) {
                g_o[(size_t)gr0 * C_DIM + col]     = oacc[mt][nt][0] * inv0;
                g_o[(size_t)gr0 * C_DIM + col + 1] = oacc[mt][nt][1] * inv0;
            }
            if (gr0 + 8 < S_TOK) {
                g_o[(size_t)(gr0 + 8) * C_DIM + col]     = oacc[mt][nt][2] * inv1;
                g_o[(size_t)(gr0 + 8) * C_DIM + col + 1] = oacc[mt][nt][3] * inv1;
            }
        }
    }
}

// ---------------- kernel 6: output projection + residual + transpose ----------------
__global__ void __launch_bounds__(256, 2) gemm_out_tc(
    const float* __restrict__ Wo, const float* __restrict__ bo,
    const float* __restrict__ x, float* __restrict__ outp) {
    extern __shared__ float gsm[];
    int m0 = blockIdx.y * 128, n0 = blockIdx.x * 128;
    float acc[4][4][4];
    #pragma unroll
    for (int a = 0; a < 4; a++)
        #pragma unroll
        for (int b = 0; b < 4; b++)
            #pragma unroll
            for (int cc = 0; cc < 4; cc++) acc[a][b][cc] = 0.f;

    gemm_main(g_o, Wo, m0, n0, gsm, acc);

    int wid = threadIdx.x >> 5, lane = threadIdx.x & 31;
    int wm = wid >> 2, wn = wid & 3;
    int gid = lane >> 2, tig = lane & 3;
    #pragma unroll
    for (int mt = 0; mt < 4; mt++) {
        int row = m0 + wm * 64 + mt * 16 + gid;
        #pragma unroll
        for (int nt = 0; nt < 4; nt++) {
            int col = n0 + wn * 32 + nt * 8 + tig * 2;
            float b0 = bo[col], b1 = bo[col + 1];
            if (row < S_TOK) {
                size_t i0 = (size_t)col * S_TOK + row;
                size_t i1 = (size_t)(col + 1) * S_TOK + row;
                outp[i0] = x[i0] + b0 + acc[mt][nt][0];
                outp[i1] = x[i1] + b1 + acc[mt][nt][1];
            }
            if (row + 8 < S_TOK) {
                size_t i2 = (size_t)col * S_TOK + row + 8;
                size_t i3 = (size_t)(col + 1) * S_TOK + row + 8;
                outp[i2] = x[i2] + b0 + acc[mt][nt][2];
                outp[i3] = x[i3] + b1 + acc[mt][nt][3];
            }
        }
    }
}

// ---------------- launcher ----------------
extern "C" void kernel_launch(void* const* d_in, const int* in_sizes, int n_in,
                              void* d_out, int out_size) {
    const float* x  = (const float*)d_in[0];
    const float* Wq = (const float*)d_in[1];
    const float* bq = (const float*)d_in[2];
    const float* Wk = (const float*)d_in[3];
    const float* bk = (const float*)d_in[4];
    const float* Wv = (const float*)d_in[5];
    const float* bv = (const float*)d_in[6];
    const float* Wo = (const float*)d_in[7];
    const float* bo = (const float*)d_in[8];
    const float* gq = (const float*)d_in[9];
    const float* gk = (const float*)d_in[10];
    float* out = (float*)d_out;

    ln_transpose_kernel<<<S_TOK / 32, 256>>>(x);
    rope_table_kernel<<<(S_TOK * HALF + 255) / 256, 256>>>();

    cudaFuncSetAttribute(gemm_qkv_tc, cudaFuncAttributeMaxDynamicSharedMemorySize, GEMM_SMEM);
    cudaFuncSetAttribute(gemm_out_tc, cudaFuncAttributeMaxDynamicSharedMemorySize, GEMM_SMEM);
    cudaFuncSetAttribute(flash_kernel, cudaFuncAttributeMaxDynamicSharedMemorySize, FLASH_SMEM);

    gemm_qkv_tc<<<dim3(C_DIM / 128, (S_TOK + 127) / 128, 3), 256, GEMM_SMEM>>>(
        Wq, bq, Wk, bk, Wv, bv);
    rms_rope_kernel<<<dim3(S_TOK, 2), 256>>>(gq, gk);

    flash_kernel<<<dim3((S_TOK + 127) / 128, NHEAD), 256, FLASH_SMEM>>>();

    gemm_out_tc<<<dim3(C_DIM / 128, (S_TOK + 127) / 128), 256, GEMM_SMEM>>>(Wo, bo, x, out);
}

// round 8
// speedup vs baseline: 5.2491x; 1.0273x over previous
#include <cuda_runtime.h>
#include <math.h>
#include <stdint.h>

#define S_TOK 3872
#define C_DIM 1536
#define NHEAD 12
#define DHEAD 128
#define HALF  64
#define T_DIM 8
#define H_DIM 22
#define W_DIM 22

// ---------------- scratch (device globals; no runtime allocation) ----------------
__device__ float g_xn[S_TOK * C_DIM];
__device__ float g_q [S_TOK * C_DIM];
__device__ float g_k [S_TOK * C_DIM];
__device__ float g_v [S_TOK * C_DIM];
__device__ float g_o [S_TOK * C_DIM];
__device__ float g_cos[S_TOK * HALF];
__device__ float g_sin[S_TOK * HALF];

// ---------------- helpers ----------------
__device__ __forceinline__ uint32_t smem_u32(const void* p) {
    uint32_t a;
    asm("{ .reg .u64 t; cvta.to.shared.u64 t, %1; cvt.u32.u64 %0, t; }" : "=r"(a) : "l"(p));
    return a;
}

__device__ __forceinline__ void mma8(float* c, const uint32_t* a, const uint32_t* b) {
    asm volatile(
        "mma.sync.aligned.m16n8k8.row.col.f32.tf32.tf32.f32 "
        "{%0,%1,%2,%3}, {%4,%5,%6,%7}, {%8,%9}, {%0,%1,%2,%3};"
        : "+f"(c[0]), "+f"(c[1]), "+f"(c[2]), "+f"(c[3])
        : "r"(a[0]), "r"(a[1]), "r"(a[2]), "r"(a[3]), "r"(b[0]), "r"(b[1]));
}

__device__ __forceinline__ float cvt_tf32(float x) {
    uint32_t t;
    asm("cvt.rna.tf32.f32 %0, %1;" : "=r"(t) : "f"(x));
    return __uint_as_float(t);
}

__device__ __forceinline__ float ex2(float x) {
    float y;
    asm("ex2.approx.ftz.f32 %0, %1;" : "=f"(y) : "f"(x));
    return y;
}

// ---------------- kernel 1: layernorm + (C,S) -> (S,C) transpose ----------------
__global__ void __launch_bounds__(256) ln_transpose_kernel(const float* __restrict__ x) {
    int s0 = blockIdx.x * 32;
    int sl = threadIdx.x & 31;
    int cg = threadIdx.x >> 5;

    float sum = 0.f, sq = 0.f;
    for (int c = cg; c < C_DIM; c += 8) {
        float v = x[c * S_TOK + s0 + sl];
        sum += v; sq += v * v;
    }
    __shared__ float ssum[8][32], ssq[8][32];
    ssum[cg][sl] = sum; ssq[cg][sl] = sq;
    __syncthreads();

    __shared__ float mean_s[32], rstd_s[32];
    if (cg == 0) {
        float a = 0.f, b = 0.f;
        #pragma unroll
        for (int g = 0; g < 8; g++) { a += ssum[g][sl]; b += ssq[g][sl]; }
        float m = a / C_DIM;
        float var = b / C_DIM - m * m;
        mean_s[sl] = m;
        rstd_s[sl] = rsqrtf(var + 1e-6f);
    }
    __syncthreads();

    __shared__ float tile[32][33];
    for (int c0 = 0; c0 < C_DIM; c0 += 32) {
        #pragma unroll
        for (int r = 0; r < 4; r++) {
            int cl = cg + 8 * r;
            tile[cl][sl] = x[(c0 + cl) * S_TOK + s0 + sl];
        }
        __syncthreads();
        #pragma unroll
        for (int r = 0; r < 4; r++) {
            int srow = cg + 8 * r;
            g_xn[(s0 + srow) * C_DIM + c0 + sl] =
                (tile[sl][srow] - mean_s[srow]) * rstd_s[srow];
        }
        __syncthreads();
    }
}

// ---------------- kernel 2: RoPE cos/sin table ----------------
__global__ void rope_table_kernel() {
    int idx = blockIdx.x * blockDim.x + threadIdx.x;
    if (idx >= S_TOK * HALF) return;
    int s = idx >> 6, j = idx & 63;
    int t  = s / (H_DIM * W_DIM);
    int rem = s % (H_DIM * W_DIM);
    int hh = rem / W_DIM, ww = rem % W_DIM;
    const double LT = log(10000.0);
    double a;
    if (j < 22)      a = (double)t  * exp(-(double)j        / 22.0 * LT);
    else if (j < 43) a = (double)hh * exp(-(double)(j - 22) / 21.0 * LT);
    else             a = (double)ww * exp(-(double)(j - 43) / 21.0 * LT);
    g_cos[idx] = (float)cos(a);
    g_sin[idx] = (float)sin(a);
}

// ---------------- tf32 mma GEMM core (3-stage cp.async pipeline) ----------------
#define GBK    32
#define GSTR   36
#define GBUF_F 9216
#define GEMM_SMEM (3 * GBUF_F * 4)
#define NCH    (C_DIM / GBK)

__device__ __forceinline__ void g_fill(uint32_t sbase, int buf,
                                       const float* __restrict__ A,
                                       const float* __restrict__ Bw,
                                       int m0, int n0, int k0) {
    int tid = threadIdx.x;
    uint32_t bb = sbase + (uint32_t)buf * (GBUF_F * 4);
    #pragma unroll
    for (int it = 0; it < 8; it++) {
        int idx = it * 256 + tid;
        int row = idx >> 3;
        int seg = idx & 7;
        int r   = row & 127;
        bool isB = row >= 128;
        uint32_t dst = bb + (isB ? 18432u : 0u) + (uint32_t)(r * (GSTR * 4) + seg * 16);
        int gr = (isB ? n0 : m0) + r;
        int sz = 16;
        if (!isB && gr >= S_TOK) { sz = 0; gr = 0; }
        const float* src = (isB ? Bw : A) + (size_t)gr * C_DIM + k0 + seg * 4;
        asm volatile("cp.async.cg.shared.global [%0], [%1], 16, %2;"
                     :: "r"(dst), "l"(src), "r"(sz));
    }
}

__device__ __forceinline__ void g_compute(const float* __restrict__ sm, int buf,
                                          int wm, int wn, int gid, int tig,
                                          float (&acc)[4][4][4]) {
    const float* As = sm + buf * GBUF_F;
    const float* Bs = As + 4608;
    #pragma unroll
    for (int ks = 0; ks < 4; ks++) {
        int kb = ks * 8;
        uint32_t af[4][4];
        #pragma unroll
        for (int mt = 0; mt < 4; mt++) {
            int m = wm * 64 + mt * 16 + gid;
            af[mt][0] = __float_as_uint(As[m * GSTR + kb + tig]);
            af[mt][1] = __float_as_uint(As[(m + 8) * GSTR + kb + tig]);
            af[mt][2] = __float_as_uint(As[m * GSTR + kb + 4 + tig]);
            af[mt][3] = __float_as_uint(As[(m + 8) * GSTR + kb + 4 + tig]);
        }
        uint32_t bf[4][2];
        #pragma unroll
        for (int nt = 0; nt < 4; nt++) {
            int n = wn * 32 + nt * 8 + gid;
            bf[nt][0] = __float_as_uint(Bs[n * GSTR + kb + tig]);
            bf[nt][1] = __float_as_uint(Bs[n * GSTR + kb + 4 + tig]);
        }
        #pragma unroll
        for (int mt = 0; mt < 4; mt++)
            #pragma unroll
            for (int nt = 0; nt < 4; nt++)
                mma8(acc[mt][nt], af[mt], bf[nt]);
    }
}

__device__ __forceinline__ void gemm_main(const float* __restrict__ A,
                                          const float* __restrict__ Bw,
                                          int m0, int n0, float* sm,
                                          float (&acc)[4][4][4]) {
    uint32_t sbase = smem_u32(sm);
    int tid = threadIdx.x;
    int wid = tid >> 5, lane = tid & 31;
    int wm = wid >> 2, wn = wid & 3;
    int gid = lane >> 2, tig = lane & 3;

    g_fill(sbase, 0, A, Bw, m0, n0, 0);
    asm volatile("cp.async.commit_group;");
    g_fill(sbase, 1, A, Bw, m0, n0, GBK);
    asm volatile("cp.async.commit_group;");

    int buf = 0, nbuf = 2;
    for (int c = 0; c < NCH; c++) {
        asm volatile("cp.async.wait_group 1;");
        __syncthreads();
        if (c + 2 < NCH) g_fill(sbase, nbuf, A, Bw, m0, n0, (c + 2) * GBK);
        asm volatile("cp.async.commit_group;");
        g_compute(sm, buf, wm, wn, gid, tig, acc);
        buf = (buf == 2) ? 0 : buf + 1;
        nbuf = (nbuf == 2) ? 0 : nbuf + 1;
    }
}

// ---------------- kernel 3: Q/K/V projections ----------------
__global__ void __launch_bounds__(256, 2) gemm_qkv_tc(
    const float* __restrict__ Wq, const float* __restrict__ bq,
    const float* __restrict__ Wk, const float* __restrict__ bk,
    const float* __restrict__ Wv, const float* __restrict__ bv) {
    extern __shared__ float gsm[];
    const float *Wm, *bias; float* out;
    if (blockIdx.z == 0)      { Wm = Wq; bias = bq; out = g_q; }
    else if (blockIdx.z == 1) { Wm = Wk; bias = bk; out = g_k; }
    else                      { Wm = Wv; bias = bv; out = g_v; }

    int m0 = blockIdx.y * 128, n0 = blockIdx.x * 128;
    float acc[4][4][4];
    #pragma unroll
    for (int a = 0; a < 4; a++)
        #pragma unroll
        for (int b = 0; b < 4; b++)
            #pragma unroll
            for (int cc = 0; cc < 4; cc++) acc[a][b][cc] = 0.f;

    gemm_main(g_xn, Wm, m0, n0, gsm, acc);

    int wid = threadIdx.x >> 5, lane = threadIdx.x & 31;
    int wm = wid >> 2, wn = wid & 3;
    int gid = lane >> 2, tig = lane & 3;
    #pragma unroll
    for (int mt = 0; mt < 4; mt++) {
        int row = m0 + wm * 64 + mt * 16 + gid;
        #pragma unroll
        for (int nt = 0; nt < 4; nt++) {
            int col = n0 + wn * 32 + nt * 8 + tig * 2;
            float b0 = bias[col], b1 = bias[col + 1];
            if (row < S_TOK) {
                out[(size_t)row * C_DIM + col]     = acc[mt][nt][0] + b0;
                out[(size_t)row * C_DIM + col + 1] = acc[mt][nt][1] + b1;
            }
            if (row + 8 < S_TOK) {
                out[(size_t)(row + 8) * C_DIM + col]     = acc[mt][nt][2] + b0;
                out[(size_t)(row + 8) * C_DIM + col + 1] = acc[mt][nt][3] + b1;
            }
        }
    }
}

// ---------------- kernel 4: RMSNorm + RoPE, in-place ----------------
__global__ void __launch_bounds__(256) rms_rope_kernel(const float* __restrict__ gq,
                                                       const float* __restrict__ gk) {
    int s = blockIdx.x;
    float* data    = (blockIdx.y == 0) ? g_q : g_k;
    const float* g = (blockIdx.y == 0) ? gq  : gk;

    float ss = 0.f;
    for (int c = threadIdx.x; c < C_DIM; c += 256) {
        float v = data[(size_t)s * C_DIM + c];
        ss += v * v;
    }
    __shared__ float red[256];
    red[threadIdx.x] = ss;
    __syncthreads();
    for (int off = 128; off > 0; off >>= 1) {
        if (threadIdx.x < off) red[threadIdx.x] += red[threadIdx.x + off];
        __syncthreads();
    }
    float rs = rsqrtf(red[0] / C_DIM + 1e-6f);

    for (int p = threadIdx.x; p < NHEAD * HALF; p += 256) {
        int head = p >> 6, j = p & 63;
        int cr = head * DHEAD + 2 * j, ci = cr + 1;
        float xr = data[(size_t)s * C_DIM + cr] * rs * g[cr];
        float xi = data[(size_t)s * C_DIM + ci] * rs * g[ci];
        float co = g_cos[s * HALF + j], si = g_sin[s * HALF + j];
        data[(size_t)s * C_DIM + cr] = xr * co - xi * si;
        data[(size_t)s * C_DIM + ci] = xr * si + xi * co;
    }
}

// ---------------- kernel 5: flash attention (tf32 mma, cp.async pipelined) ----------------
#define FBK   32
#define FNIT  (S_TOK / FBK)
#define QSTR  132
#define KSTRK 132
#define KSTRV 136
#define PSTR  36
#define FQ_F  (128 * QSTR)
#define FK_F  (FBK * KSTRK)
#define FV_F  (FBK * KSTRV)
#define FP_F  (128 * PSTR)
#define FLASH_F (FQ_F + 2 * FK_F + 2 * FV_F + 2 * FP_F + 256)
#define FLASH_SMEM (FLASH_F * 4)

extern __shared__ float fsm[];

__device__ __forceinline__ void f_fill(uint32_t dstbase, int stride,
                                       const float* __restrict__ src, int kc, int h) {
    int tid = threadIdx.x;
    #pragma unroll
    for (int it = 0; it < 4; it++) {
        int idx = it * 256 + tid;
        int row = idx >> 5, seg = idx & 31;
        uint32_t dst = dstbase + (uint32_t)(row * stride + seg * 4) * 4u;
        const float* s = src + (size_t)(kc * FBK + row) * C_DIM + h * DHEAD + seg * 4;
        asm volatile("cp.async.cg.shared.global [%0], [%1], 16;" :: "r"(dst), "l"(s));
    }
}

__global__ void __launch_bounds__(256) flash_kernel() {
    float* Qs   = fsm;
    float* Ks   = Qs + FQ_F;
    float* Vs   = Ks + 2 * FK_F;
    float* Ps   = Vs + 2 * FV_F;
    float* alsm = Ps + 2 * FP_F;
    float* lsm  = alsm + 128;

    uint32_t sb = smem_u32(fsm);
    uint32_t ks_base = sb + FQ_F * 4;
    uint32_t vs_base = sb + (FQ_F + 2 * FK_F) * 4;

    int q0 = blockIdx.x * 128;
    int h  = blockIdx.y;
    int tid = threadIdx.x;
    int wid = tid >> 5, lane = tid & 31;
    int gid = lane >> 2, tig = lane & 3;
    // fold 1/sqrt(d) AND log2(e) into Q so softmax uses raw ex2
    const float scale = 0.08838834764831845f * 1.44269504088896341f;

    #pragma unroll
    for (int it = 0; it < 16; it++) {
        int i4 = it * 256 + tid;
        int row = i4 >> 5;
        int c4 = (i4 & 31) << 2;
        float4 v = (q0 + row < S_TOK)
            ? *(const float4*)&g_q[(size_t)(q0 + row) * C_DIM + h * DHEAD + c4]
            : make_float4(0.f, 0.f, 0.f, 0.f);
        v.x *= scale; v.y *= scale; v.z *= scale; v.w *= scale;
        *(float4*)&Qs[row * QSTR + c4] = v;
    }

    f_fill(ks_base, KSTRK, g_k, 0, h);
    f_fill(vs_base, KSTRV, g_v, 0, h);
    asm volatile("cp.async.commit_group;");
    f_fill(ks_base + FK_F * 4, KSTRK, g_k, 1, h);
    asm volatile("cp.async.commit_group;");

    int row2 = tid >> 1, part = tid & 1;
    float m_reg = -1e30f, l_reg = 0.f;

    int wmP = wid >> 2, wnP = wid & 3;
    float oacc[4][4][4];
    #pragma unroll
    for (int a = 0; a < 4; a++)
        #pragma unroll
        for (int b = 0; b < 4; b++)
            #pragma unroll
            for (int cc = 0; cc < 4; cc++) oacc[a][b][cc] = 0.f;

    int wmS = wid >> 1, wnS = wid & 1;

    asm volatile("cp.async.wait_group 1;");
    __syncthreads();

    for (int c = 0; c < FNIT; c++) {
        const float* Kb = Ks + (c & 1) * FK_F;
        const float* Vb = Vs + (c & 1) * FV_F;
        float* Sb = Ps + (c & 1) * FP_F;

        // ---- S = Q @ K^T : [128][32] ----
        float sacc[2][2][4];
        #pragma unroll
        for (int a = 0; a < 2; a++)
            #pragma unroll
            for (int b = 0; b < 2; b++)
                #pragma unroll
                for (int cc = 0; cc < 4; cc++) sacc[a][b][cc] = 0.f;

        #pragma unroll
        for (int ks = 0; ks < 16; ks++) {
            int kb = ks * 8;
            uint32_t af[2][4];
            #pragma unroll
            for (int mt = 0; mt < 2; mt++) {
                int m = wmS * 32 + mt * 16 + gid;
                af[mt][0] = __float_as_uint(Qs[m * QSTR + kb + tig]);
                af[mt][1] = __float_as_uint(Qs[(m + 8) * QSTR + kb + tig]);
                af[mt][2] = __float_as_uint(Qs[m * QSTR + kb + 4 + tig]);
                af[mt][3] = __float_as_uint(Qs[(m + 8) * QSTR + kb + 4 + tig]);
            }
            uint32_t bf[2][2];
            #pragma unroll
            for (int nt = 0; nt < 2; nt++) {
                int n = wnS * 16 + nt * 8 + gid;
                bf[nt][0] = __float_as_uint(Kb[n * KSTRK + kb + tig]);
                bf[nt][1] = __float_as_uint(Kb[n * KSTRK + kb + 4 + tig]);
            }
            #pragma unroll
            for (int mt = 0; mt < 2; mt++)
                #pragma unroll
                for (int nt = 0; nt < 2; nt++)
                    mma8(sacc[mt][nt], af[mt], bf[nt]);
        }
        #pragma unroll
        for (int mt = 0; mt < 2; mt++) {
            int row = wmS * 32 + mt * 16 + gid;
            #pragma unroll
            for (int nt = 0; nt < 2; nt++) {
                int col = wnS * 16 + nt * 8 + tig * 2;
                Sb[row * PSTR + col]           = sacc[mt][nt][0];
                Sb[row * PSTR + col + 1]       = sacc[mt][nt][1];
                Sb[(row + 8) * PSTR + col]     = sacc[mt][nt][2];
                Sb[(row + 8) * PSTR + col + 1] = sacc[mt][nt][3];
            }
        }
        __syncthreads();

        if (c + 2 < FNIT) f_fill(ks_base + (c & 1) * FK_F * 4, KSTRK, g_k, c + 2, h);
        if (c + 1 < FNIT) f_fill(vs_base + ((c + 1) & 1) * FV_F * 4, KSTRV, g_v, c + 1, h);
        asm volatile("cp.async.commit_group;");

        // ---- softmax (base-2 domain) ----
        {
            float* p0 = &Sb[row2 * PSTR + part * 16];
            float4 v0 = *(float4*)&p0[0], v1 = *(float4*)&p0[4];
            float4 v2 = *(float4*)&p0[8], v3 = *(float4*)&p0[12];
            float mx = fmaxf(fmaxf(fmaxf(v0.x, v0.y), fmaxf(v0.z, v0.w)),
                             fmaxf(fmaxf(v1.x, v1.y), fmaxf(v1.z, v1.w)));
            mx = fmaxf(mx, fmaxf(fmaxf(fmaxf(v2.x, v2.y), fmaxf(v2.z, v2.w)),
                                 fmaxf(fmaxf(v3.x, v3.y), fmaxf(v3.z, v3.w))));
            mx = fmaxf(mx, __shfl_xor_sync(0xFFFFFFFFu, mx, 1));
            float mnew = fmaxf(m_reg, mx);
            float alpha = ex2(m_reg - mnew);
            m_reg = mnew;

            float4 e0, e1, e2, e3;
            e0.x = ex2(v0.x - mnew); e0.y = ex2(v0.y - mnew);
            e0.z = ex2(v0.z - mnew); e0.w = ex2(v0.w - mnew);
            e1.x = ex2(v1.x - mnew); e1.y = ex2(v1.y - mnew);
            e1.z = ex2(v1.z - mnew); e1.w = ex2(v1.w - mnew);
            e2.x = ex2(v2.x - mnew); e2.y = ex2(v2.y - mnew);
            e2.z = ex2(v2.z - mnew); e2.w = ex2(v2.w - mnew);
            e3.x = ex2(v3.x - mnew); e3.y = ex2(v3.y - mnew);
            e3.z = ex2(v3.z - mnew); e3.w = ex2(v3.w - mnew);
            float ps = (e0.x + e0.y + e0.z + e0.w) + (e1.x + e1.y + e1.z + e1.w)
                     + (e2.x + e2.y + e2.z + e2.w) + (e3.x + e3.y + e3.z + e3.w);
            e0.x = cvt_tf32(e0.x); e0.y = cvt_tf32(e0.y); e0.z = cvt_tf32(e0.z); e0.w = cvt_tf32(e0.w);
            e1.x = cvt_tf32(e1.x); e1.y = cvt_tf32(e1.y); e1.z = cvt_tf32(e1.z); e1.w = cvt_tf32(e1.w);
            e2.x = cvt_tf32(e2.x); e2.y = cvt_tf32(e2.y); e2.z = cvt_tf32(e2.z); e2.w = cvt_tf32(e2.w);
            e3.x = cvt_tf32(e3.x); e3.y = cvt_tf32(e3.y); e3.z = cvt_tf32(e3.z); e3.w = cvt_tf32(e3.w);
            *(float4*)&p0[0] = e0; *(float4*)&p0[4] = e1;
            *(float4*)&p0[8] = e2; *(float4*)&p0[12] = e3;

            ps += __shfl_xor_sync(0xFFFFFFFFu, ps, 1);
            l_reg = l_reg * alpha + ps;
            if (part == 0) alsm[row2] = alpha;
        }

        asm volatile("cp.async.wait_group 1;");
        __syncthreads();

        // ---- PV ----
        #pragma unroll
        for (int mt = 0; mt < 4; mt++) {
            int r = wmP * 64 + mt * 16 + gid;
            float al0 = alsm[r], al1 = alsm[r + 8];
            #pragma unroll
            for (int nt = 0; nt < 4; nt++) {
                oacc[mt][nt][0] *= al0; oacc[mt][nt][1] *= al0;
                oacc[mt][nt][2] *= al1; oacc[mt][nt][3] *= al1;
            }
        }
        #pragma unroll
        for (int ks = 0; ks < 4; ks++) {
            int kb = ks * 8;
            uint32_t af[4][4];
            #pragma unroll
            for (int mt = 0; mt < 4; mt++) {
                int m = wmP * 64 + mt * 16 + gid;
                af[mt][0] = __float_as_uint(Sb[m * PSTR + kb + tig]);
                af[mt][1] = __float_as_uint(Sb[(m + 8) * PSTR + kb + tig]);
                af[mt][2] = __float_as_uint(Sb[m * PSTR + kb + 4 + tig]);
                af[mt][3] = __float_as_uint(Sb[(m + 8) * PSTR + kb + 4 + tig]);
            }
            uint32_t bf[4][2];
            #pragma unroll
            for (int nt = 0; nt < 4; nt++) {
                int n = wnP * 32 + nt * 8 + gid;
                bf[nt][0] = __float_as_uint(Vb[(kb + tig) * KSTRV + n]);
                bf[nt][1] = __float_as_uint(Vb[(kb + 4 + tig) * KSTRV + n]);
            }
            #pragma unroll
            for (int mt = 0; mt < 4; mt++)
                #pragma unroll
                for (int nt = 0; nt < 4; nt++)
                    mma8(oacc[mt][nt], af[mt], bf[nt]);
        }
    }

    if (part == 0) lsm[row2] = l_reg;
    __syncthreads();

    #pragma unroll
    for (int mt = 0; mt < 4; mt++) {
        int r = wmP * 64 + mt * 16 + gid;
        float inv0 = 1.f / lsm[r];
        float inv1 = 1.f / lsm[r + 8];
        int gr0 = q0 + r;
        #pragma unroll
        for (int nt = 0; nt < 4; nt++) {
            int col = h * DHEAD + wnP * 32 + nt * 8 + tig * 2;
            if (gr0 < S_TOK) {
                g_o[(size_t)gr0 * C_DIM + col]     = oacc[mt][nt][0] * inv0;
                g_o[(size_t)gr0 * C_DIM + col + 1] = oacc[mt][nt][1] * inv0;
            }
            if (gr0 + 8 < S_TOK) {
                g_o[(size_t)(gr0 + 8) * C_DIM + col]     = oacc[mt][nt][2] * inv1;
                g_o[(size_t)(gr0 + 8) * C_DIM + col + 1] = oacc[mt][nt][3] * inv1;
            }
        }
    }
}

// ---------------- kernel 6: output projection + residual + transpose ----------------
#define TSTR 132
__global__ void __launch_bounds__(256, 2) gemm_out_tc(
    const float* __restrict__ Wo, const float* __restrict__ bo,
    const float* __restrict__ x, float* __restrict__ outp) {
    extern __shared__ float gsm[];
    int m0 = blockIdx.y * 128, n0 = blockIdx.x * 128;
    float acc[4][4][4];
    #pragma unroll
    for (int a = 0; a < 4; a++)
        #pragma unroll
        for (int b = 0; b < 4; b++)
            #pragma unroll
            for (int cc = 0; cc < 4; cc++) acc[a][b][cc] = 0.f;

    gemm_main(g_o, Wo, m0, n0, gsm, acc);

    // drain all cp.async, then reuse gsm as transpose staging: gsm[col*TSTR + row]
    asm volatile("cp.async.wait_group 0;");
    __syncthreads();

    int wid = threadIdx.x >> 5, lane = threadIdx.x & 31;
    int wm = wid >> 2, wn = wid & 3;
    int gid = lane >> 2, tig = lane & 3;
    #pragma unroll
    for (int mt = 0; mt < 4; mt++) {
        int row = wm * 64 + mt * 16 + gid;
        #pragma unroll
        for (int nt = 0; nt < 4; nt++) {
            int col = wn * 32 + nt * 8 + tig * 2;
            gsm[col * TSTR + row]           = acc[mt][nt][0];
            gsm[(col + 1) * TSTR + row]     = acc[mt][nt][1];
            gsm[col * TSTR + row + 8]       = acc[mt][nt][2];
            gsm[(col + 1) * TSTR + row + 8] = acc[mt][nt][3];
        }
    }
    __syncthreads();

    // each warp writes 16 columns; each column = 128 contiguous rows (float4)
    #pragma unroll
    for (int cc2 = 0; cc2 < 16; cc2++) {
        int col = wid * 16 + cc2;
        int gcol = n0 + col;
        float b = bo[gcol];
        int grow = m0 + lane * 4;
        if (grow < S_TOK) {
            float4 a = *(float4*)&gsm[col * TSTR + lane * 4];
            size_t gi = (size_t)gcol * S_TOK + grow;
            float4 xv = *(const float4*)&x[gi];
            float4 o;
            o.x = xv.x + b + a.x; o.y = xv.y + b + a.y;
            o.z = xv.z + b + a.z; o.w = xv.w + b + a.w;
            *(float4*)&outp[gi] = o;
        }
    }
}

// ---------------- launcher ----------------
extern "C" void kernel_launch(void* const* d_in, const int* in_sizes, int n_in,
                              void* d_out, int out_size) {
    const float* x  = (const float*)d_in[0];
    const float* Wq = (const float*)d_in[1];
    const float* bq = (const float*)d_in[2];
    const float* Wk = (const float*)d_in[3];
    const float* bk = (const float*)d_in[4];
    const float* Wv = (const float*)d_in[5];
    const float* bv = (const float*)d_in[6];
    const float* Wo = (const float*)d_in[7];
    const float* bo = (const float*)d_in[8];
    const float* gq = (const float*)d_in[9];
    const float* gk = (const float*)d_in[10];
    float* out = (float*)d_out;

    ln_transpose_kernel<<<S_TOK / 32, 256>>>(x);
    rope_table_kernel<<<(S_TOK * HALF + 255) / 256, 256>>>();

    cudaFuncSetAttribute(gemm_qkv_tc, cudaFuncAttributeMaxDynamicSharedMemorySize, GEMM_SMEM);
    cudaFuncSetAttribute(gemm_out_tc, cudaFuncAttributeMaxDynamicSharedMemorySize, GEMM_SMEM);
    cudaFuncSetAttribute(flash_kernel, cudaFuncAttributeMaxDynamicSharedMemorySize, FLASH_SMEM);

    gemm_qkv_tc<<<dim3(C_DIM / 128, (S_TOK + 127) / 128, 3), 256, GEMM_SMEM>>>(
        Wq, bq, Wk, bk, Wv, bv);
    rms_rope_kernel<<<dim3(S_TOK, 2), 256>>>(gq, gk);

    flash_kernel<<<dim3((S_TOK + 127) / 128, NHEAD), 256, FLASH_SMEM>>>();

    gemm_out_tc<<<dim3(C_DIM / 128, (S_TOK + 127) / 128), 256, GEMM_SMEM>>>(Wo, bo, x, out);
}

// round 9
// speedup vs baseline: 8.7398x; 1.6650x over previous
#include <cuda_runtime.h>
#include <cuda_bf16.h>
#include <math.h>
#include <stdint.h>

#define S_TOK 3872
#define C_DIM 1536
#define NHEAD 12
#define DHEAD 128
#define HALF  64
#define T_DIM 8
#define H_DIM 22
#define W_DIM 22
#define CPAIR (C_DIM / 2)   // 768 uint32 pairs per row

// ---------------- scratch (device globals; no runtime allocation) ----------------
__device__ __nv_bfloat16 g_xn[S_TOK * C_DIM];
__device__ __nv_bfloat16 g_wq[C_DIM * C_DIM];
__device__ __nv_bfloat16 g_wk[C_DIM * C_DIM];
__device__ __nv_bfloat16 g_wv[C_DIM * C_DIM];
__device__ float    g_q [S_TOK * C_DIM];
__device__ float    g_k [S_TOK * C_DIM];
__device__ uint32_t g_v32 [S_TOK * CPAIR];
__device__ uint32_t g_qb32[S_TOK * CPAIR];
__device__ uint32_t g_kb32[S_TOK * CPAIR];
__device__ float    g_o [S_TOK * C_DIM];
__device__ float g_cos[S_TOK * HALF];
__device__ float g_sin[S_TOK * HALF];

// ---------------- helpers ----------------
__device__ __forceinline__ uint32_t smem_u32(const void* p) {
    uint32_t a;
    asm("{ .reg .u64 t; cvta.to.shared.u64 t, %1; cvt.u32.u64 %0, t; }" : "=r"(a) : "l"(p));
    return a;
}

// tf32 m16n8k8 (kept for output projection)
__device__ __forceinline__ void mma8(float* c, const uint32_t* a, const uint32_t* b) {
    asm volatile(
        "mma.sync.aligned.m16n8k8.row.col.f32.tf32.tf32.f32 "
        "{%0,%1,%2,%3}, {%4,%5,%6,%7}, {%8,%9}, {%0,%1,%2,%3};"
        : "+f"(c[0]), "+f"(c[1]), "+f"(c[2]), "+f"(c[3])
        : "r"(a[0]), "r"(a[1]), "r"(a[2]), "r"(a[3]), "r"(b[0]), "r"(b[1]));
}

// bf16 m16n8k16
__device__ __forceinline__ void mma16(float* c, const uint32_t* a, const uint32_t* b) {
    asm volatile(
        "mma.sync.aligned.m16n8k16.row.col.f32.bf16.bf16.f32 "
        "{%0,%1,%2,%3}, {%4,%5,%6,%7}, {%8,%9}, {%0,%1,%2,%3};"
        : "+f"(c[0]), "+f"(c[1]), "+f"(c[2]), "+f"(c[3])
        : "r"(a[0]), "r"(a[1]), "r"(a[2]), "r"(a[3]), "r"(b[0]), "r"(b[1]));
}

// pack two f32 -> bf16x2 (lo = first arg in low halfword)
__device__ __forceinline__ uint32_t packbf(float lo, float hi) {
    uint32_t r;
    asm("cvt.rn.bf16x2.f32 %0, %1, %2;" : "=r"(r) : "f"(hi), "f"(lo));
    return r;
}

__device__ __forceinline__ float ex2(float x) {
    float y;
    asm("ex2.approx.ftz.f32 %0, %1;" : "=f"(y) : "f"(x));
    return y;
}

// ---------------- kernel 1: layernorm + transpose -> bf16 g_xn ----------------
__global__ void __launch_bounds__(256) ln_transpose_kernel(const float* __restrict__ x) {
    int s0 = blockIdx.x * 32;
    int sl = threadIdx.x & 31;
    int cg = threadIdx.x >> 5;

    float sum = 0.f, sq = 0.f;
    for (int c = cg; c < C_DIM; c += 8) {
        float v = x[c * S_TOK + s0 + sl];
        sum += v; sq += v * v;
    }
    __shared__ float ssum[8][32], ssq[8][32];
    ssum[cg][sl] = sum; ssq[cg][sl] = sq;
    __syncthreads();

    __shared__ float mean_s[32], rstd_s[32];
    if (cg == 0) {
        float a = 0.f, b = 0.f;
        #pragma unroll
        for (int g = 0; g < 8; g++) { a += ssum[g][sl]; b += ssq[g][sl]; }
        float m = a / C_DIM;
        float var = b / C_DIM - m * m;
        mean_s[sl] = m;
        rstd_s[sl] = rsqrtf(var + 1e-6f);
    }
    __syncthreads();

    __shared__ float tile[32][33];
    for (int c0 = 0; c0 < C_DIM; c0 += 32) {
        #pragma unroll
        for (int r = 0; r < 4; r++) {
            int cl = cg + 8 * r;
            tile[cl][sl] = x[(c0 + cl) * S_TOK + s0 + sl];
        }
        __syncthreads();
        #pragma unroll
        for (int r = 0; r < 4; r++) {
            int srow = cg + 8 * r;
            g_xn[(s0 + srow) * C_DIM + c0 + sl] =
                __float2bfloat16((tile[sl][srow] - mean_s[srow]) * rstd_s[srow]);
        }
        __syncthreads();
    }
}

// ---------------- kernel 2: RoPE cos/sin table ----------------
__global__ void rope_table_kernel() {
    int idx = blockIdx.x * blockDim.x + threadIdx.x;
    if (idx >= S_TOK * HALF) return;
    int s = idx >> 6, j = idx & 63;
    int t  = s / (H_DIM * W_DIM);
    int rem = s % (H_DIM * W_DIM);
    int hh = rem / W_DIM, ww = rem % W_DIM;
    const double LT = log(10000.0);
    double a;
    if (j < 22)      a = (double)t  * exp(-(double)j        / 22.0 * LT);
    else if (j < 43) a = (double)hh * exp(-(double)(j - 22) / 21.0 * LT);
    else             a = (double)ww * exp(-(double)(j - 43) / 21.0 * LT);
    g_cos[idx] = (float)cos(a);
    g_sin[idx] = (float)sin(a);
}

// ---------------- kernel 2b: convert Wq/Wk/Wv to bf16 ----------------
__global__ void __launch_bounds__(256) convert_w_kernel(
    const float* __restrict__ Wq, const float* __restrict__ Wk,
    const float* __restrict__ Wv) {
    int idx = blockIdx.x * 256 + threadIdx.x;           // float4 index
    const float* src = (blockIdx.y == 0) ? Wq : (blockIdx.y == 1) ? Wk : Wv;
    __nv_bfloat16* dst = (blockIdx.y == 0) ? g_wq : (blockIdx.y == 1) ? g_wk : g_wv;
    float4 v = *(const float4*)&src[(size_t)idx * 4];
    uint2 o;
    o.x = packbf(v.x, v.y);
    o.y = packbf(v.z, v.w);
    *(uint2*)&dst[(size_t)idx * 4] = o;
}

// ---------------- bf16 GEMM core (3-stage cp.async, BK=64) ----------------
#define BBK    64
#define BSTR   36            // uint32 pair stride (32 used + 4 pad)
#define BBUF_W 9216          // uint32 words per buffer (A 4608 + B 4608)
#define GEMMB_SMEM (3 * BBUF_W * 4)
#define BNCH   (C_DIM / BBK) // 24

__device__ __forceinline__ void gb_fill(uint32_t sbase, int buf,
                                        const __nv_bfloat16* __restrict__ A,
                                        const __nv_bfloat16* __restrict__ Bw,
                                        int m0, int n0, int k0) {
    int tid = threadIdx.x;
    uint32_t bb = sbase + (uint32_t)buf * (BBUF_W * 4);
    #pragma unroll
    for (int it = 0; it < 8; it++) {
        int idx = it * 256 + tid;
        int row = idx >> 3;
        int seg = idx & 7;               // 16B = 8 bf16
        int r   = row & 127;
        bool isB = row >= 128;
        uint32_t dst = bb + (isB ? 18432u : 0u) + (uint32_t)(r * (BSTR * 4) + seg * 16);
        int gr = (isB ? n0 : m0) + r;
        int sz = 16;
        if (!isB && gr >= S_TOK) { sz = 0; gr = 0; }
        const __nv_bfloat16* src = (isB ? Bw : A) + (size_t)gr * C_DIM + k0 + seg * 8;
        asm volatile("cp.async.cg.shared.global [%0], [%1], 16, %2;"
                     :: "r"(dst), "l"(src), "r"(sz));
    }
}

__device__ __forceinline__ void gb_compute(const uint32_t* __restrict__ sm, int buf,
                                           int wm, int wn, int gid, int tig,
                                           float (&acc)[4][4][4]) {
    const uint32_t* As = sm + buf * BBUF_W;
    const uint32_t* Bs = As + 4608;
    #pragma unroll
    for (int ks = 0; ks < 4; ks++) {
        int kp = ks * 8;
        uint32_t af[4][4];
        #pragma unroll
        for (int mt = 0; mt < 4; mt++) {
            int m = wm * 64 + mt * 16 + gid;
            af[mt][0] = As[m * BSTR + kp + tig];
            af[mt][1] = As[(m + 8) * BSTR + kp + tig];
            af[mt][2] = As[m * BSTR + kp + tig + 4];
            af[mt][3] = As[(m + 8) * BSTR + kp + tig + 4];
        }
        uint32_t bf[4][2];
        #pragma unroll
        for (int nt = 0; nt < 4; nt++) {
            int n = wn * 32 + nt * 8 + gid;
            bf[nt][0] = Bs[n * BSTR + kp + tig];
            bf[nt][1] = Bs[n * BSTR + kp + tig + 4];
        }
        #pragma unroll
        for (int mt = 0; mt < 4; mt++)
            #pragma unroll
            for (int nt = 0; nt < 4; nt++)
                mma16(acc[mt][nt], af[mt], bf[nt]);
    }
}

// ---------------- kernel 3: Q/K/V projections (bf16) ----------------
__global__ void __launch_bounds__(256, 2) gemm_qkv_b(
    const float* __restrict__ bq, const float* __restrict__ bk,
    const float* __restrict__ bv) {
    extern __shared__ uint32_t gsb[];
    const __nv_bfloat16* Wm;
    const float* bias;
    if (blockIdx.z == 0)      { Wm = g_wq; bias = bq; }
    else if (blockIdx.z == 1) { Wm = g_wk; bias = bk; }
    else                      { Wm = g_wv; bias = bv; }

    int m0 = blockIdx.y * 128, n0 = blockIdx.x * 128;
    float acc[4][4][4];
    #pragma unroll
    for (int a = 0; a < 4; a++)
        #pragma unroll
        for (int b = 0; b < 4; b++)
            #pragma unroll
            for (int cc = 0; cc < 4; cc++) acc[a][b][cc] = 0.f;

    uint32_t sbase = smem_u32(gsb);
    int tid = threadIdx.x;
    int wid = tid >> 5, lane = tid & 31;
    int wm = wid >> 2, wn = wid & 3;
    int gid = lane >> 2, tig = lane & 3;

    gb_fill(sbase, 0, g_xn, Wm, m0, n0, 0);
    asm volatile("cp.async.commit_group;");
    gb_fill(sbase, 1, g_xn, Wm, m0, n0, BBK);
    asm volatile("cp.async.commit_group;");

    int buf = 0, nbuf = 2;
    for (int c = 0; c < BNCH; c++) {
        asm volatile("cp.async.wait_group 1;");
        __syncthreads();
        if (c + 2 < BNCH) gb_fill(sbase, nbuf, g_xn, Wm, m0, n0, (c + 2) * BBK);
        asm volatile("cp.async.commit_group;");
        gb_compute(gsb, buf, wm, wn, gid, tig, acc);
        buf = (buf == 2) ? 0 : buf + 1;
        nbuf = (nbuf == 2) ? 0 : nbuf + 1;
    }

    #pragma unroll
    for (int mt = 0; mt < 4; mt++) {
        int row = m0 + wm * 64 + mt * 16 + gid;
        #pragma unroll
        for (int nt = 0; nt < 4; nt++) {
            int col = n0 + wn * 32 + nt * 8 + tig * 2;
            float b0 = bias[col], b1 = bias[col + 1];
            if (blockIdx.z == 2) {
                if (row < S_TOK)
                    g_v32[(size_t)row * CPAIR + (col >> 1)] =
                        packbf(acc[mt][nt][0] + b0, acc[mt][nt][1] + b1);
                if (row + 8 < S_TOK)
                    g_v32[(size_t)(row + 8) * CPAIR + (col >> 1)] =
                        packbf(acc[mt][nt][2] + b0, acc[mt][nt][3] + b1);
            } else {
                float* out = (blockIdx.z == 0) ? g_q : g_k;
                if (row < S_TOK) {
                    out[(size_t)row * C_DIM + col]     = acc[mt][nt][0] + b0;
                    out[(size_t)row * C_DIM + col + 1] = acc[mt][nt][1] + b1;
                }
                if (row + 8 < S_TOK) {
                    out[(size_t)(row + 8) * C_DIM + col]     = acc[mt][nt][2] + b0;
                    out[(size_t)(row + 8) * C_DIM + col + 1] = acc[mt][nt][3] + b1;
                }
            }
        }
    }
}

// ---------------- kernel 4: RMSNorm + RoPE -> bf16 pairs ----------------
__global__ void __launch_bounds__(256) rms_rope_kernel(const float* __restrict__ gq,
                                                       const float* __restrict__ gk) {
    int s = blockIdx.x;
    const float* data = (blockIdx.y == 0) ? g_q : g_k;
    const float* g    = (blockIdx.y == 0) ? gq  : gk;
    uint32_t* outp    = (blockIdx.y == 0) ? g_qb32 : g_kb32;
    // Q gets 1/sqrt(d) * log2(e) folded in
    float s2 = (blockIdx.y == 0) ? 0.08838834764831845f * 1.44269504088896341f : 1.f;

    float ss = 0.f;
    for (int c = threadIdx.x; c < C_DIM; c += 256) {
        float v = data[(size_t)s * C_DIM + c];
        ss += v * v;
    }
    __shared__ float red[256];
    red[threadIdx.x] = ss;
    __syncthreads();
    for (int off = 128; off > 0; off >>= 1) {
        if (threadIdx.x < off) red[threadIdx.x] += red[threadIdx.x + off];
        __syncthreads();
    }
    float rs = rsqrtf(red[0] / C_DIM + 1e-6f);

    for (int p = threadIdx.x; p < NHEAD * HALF; p += 256) {
        int head = p >> 6, j = p & 63;
        int cr = head * DHEAD + 2 * j, ci = cr + 1;
        float xr = data[(size_t)s * C_DIM + cr] * rs * g[cr];
        float xi = data[(size_t)s * C_DIM + ci] * rs * g[ci];
        float co = g_cos[s * HALF + j], si = g_sin[s * HALF + j];
        float orr = (xr * co - xi * si) * s2;
        float oii = (xr * si + xi * co) * s2;
        outp[(size_t)s * CPAIR + head * HALF + j] = packbf(orr, oii);
    }
}

// ---------------- kernel 5: flash attention (bf16 mma, single S/P, 2 CTA/SM) ----------------
#define FBK   32
#define FNIT  (S_TOK / FBK)   // 121
#define QS2   68              // pair strides (mod 32 == 4 -> conflict-free)
#define KS2   68
#define VS2   68
#define SSTRf 36
#define PS2   20
#define FQ_W  (128 * QS2)     // 8704
#define FK_W  (FBK * KS2)     // 2176
#define FV_W  (FBK * VS2)     // 2176
#define FS_W  (128 * SSTRf)   // 4608
#define FP_W  (128 * PS2)     // 2560
#define FLASH_W (FQ_W + 2 * FK_W + 2 * FV_W + FS_W + FP_W + 256)
#define FLASH_SMEM (FLASH_W * 4)

__device__ __forceinline__ void f_fillb(uint32_t dstbase, const uint32_t* __restrict__ src,
                                        int kc, int h) {
    int tid = threadIdx.x;
    #pragma unroll
    for (int it = 0; it < 2; it++) {
        int idx = it * 256 + tid;       // 0..511
        int row = idx >> 4, seg = idx & 15;
        uint32_t dst = dstbase + (uint32_t)(row * KS2 + seg * 4) * 4u;
        const uint32_t* s = src + (size_t)(kc * FBK + row) * CPAIR + h * HALF + seg * 4;
        asm volatile("cp.async.cg.shared.global [%0], [%1], 16;" :: "r"(dst), "l"(s));
    }
}

__global__ void __launch_bounds__(256, 2) flash_kernel() {
    extern __shared__ uint32_t fsw[];
    uint32_t* Qs = fsw;
    uint32_t* Ks = Qs + FQ_W;
    uint32_t* Vs = Ks + 2 * FK_W;
    float*    Ss = (float*)(Vs + 2 * FV_W);
    uint32_t* Ps = (uint32_t*)(Ss + FS_W);
    float* alsm  = (float*)(Ps + FP_W);
    float* lsm   = alsm + 128;

    uint32_t sb   = smem_u32(fsw);
    uint32_t ks_b = sb + FQ_W * 4;
    uint32_t vs_b = ks_b + 2 * FK_W * 4;

    int q0 = blockIdx.x * 128;
    int h  = blockIdx.y;
    int tid = threadIdx.x;
    int wid = tid >> 5, lane = tid & 31;
    int gid = lane >> 2, tig = lane & 3;

    // Q fill (bf16 pairs, already scaled)
    #pragma unroll
    for (int it = 0; it < 8; it++) {
        int idx = it * 256 + tid;       // 0..2047
        int row = idx >> 4, seg = idx & 15;
        uint32_t dst = sb + (uint32_t)(row * QS2 + seg * 4) * 4u;
        int gr = q0 + row;
        int sz = (gr < S_TOK) ? 16 : 0;
        if (gr >= S_TOK) gr = 0;
        const uint32_t* s = g_qb32 + (size_t)gr * CPAIR + h * HALF + seg * 4;
        asm volatile("cp.async.cg.shared.global [%0], [%1], 16, %2;"
                     :: "r"(dst), "l"(s), "r"(sz));
    }

    f_fillb(ks_b, g_kb32, 0, h);
    f_fillb(vs_b, g_v32, 0, h);
    asm volatile("cp.async.commit_group;");
    f_fillb(ks_b + FK_W * 4, g_kb32, 1, h);
    asm volatile("cp.async.commit_group;");

    int row2 = tid >> 1, part = tid & 1;
    float m_reg = -1e30f, l_reg = 0.f;

    int wmP = wid >> 2, wnP = wid & 3;     // PV: 2m x 4n, warp tile 64x32
    float oacc[4][4][4];
    #pragma unroll
    for (int a = 0; a < 4; a++)
        #pragma unroll
        for (int b = 0; b < 4; b++)
            #pragma unroll
            for (int cc = 0; cc < 4; cc++) oacc[a][b][cc] = 0.f;

    int wmS = wid >> 1, wnS = wid & 1;     // S: 4m x 2n, warp tile 32x16

    asm volatile("cp.async.wait_group 1;");
    __syncthreads();

    for (int c = 0; c < FNIT; c++) {
        const uint32_t* Kb = Ks + (c & 1) * FK_W;
        uint32_t vbase = vs_b + (uint32_t)(c & 1) * FV_W * 4;

        // ---- S = Q @ K^T : [128][32] (bf16, 8 k16-steps) ----
        float sacc[2][2][4];
        #pragma unroll
        for (int a = 0; a < 2; a++)
            #pragma unroll
            for (int b = 0; b < 2; b++)
                #pragma unroll
                for (int cc = 0; cc < 4; cc++) sacc[a][b][cc] = 0.f;

        #pragma unroll
        for (int ks = 0; ks < 8; ks++) {
            int kp = ks * 8;
            uint32_t af[2][4];
            #pragma unroll
            for (int mt = 0; mt < 2; mt++) {
                int m = wmS * 32 + mt * 16 + gid;
                af[mt][0] = Qs[m * QS2 + kp + tig];
                af[mt][1] = Qs[(m + 8) * QS2 + kp + tig];
                af[mt][2] = Qs[m * QS2 + kp + tig + 4];
                af[mt][3] = Qs[(m + 8) * QS2 + kp + tig + 4];
            }
            uint32_t bf[2][2];
            #pragma unroll
            for (int nt = 0; nt < 2; nt++) {
                int n = wnS * 16 + nt * 8 + gid;
                bf[nt][0] = Kb[n * KS2 + kp + tig];
                bf[nt][1] = Kb[n * KS2 + kp + tig + 4];
            }
            #pragma unroll
            for (int mt = 0; mt < 2; mt++)
                #pragma unroll
                for (int nt = 0; nt < 2; nt++)
                    mma16(sacc[mt][nt], af[mt], bf[nt]);
        }
        #pragma unroll
        for (int mt = 0; mt < 2; mt++) {
            int row = wmS * 32 + mt * 16 + gid;
            #pragma unroll
            for (int nt = 0; nt < 2; nt++) {
                int col = wnS * 16 + nt * 8 + tig * 2;
                Ss[row * SSTRf + col]           = sacc[mt][nt][0];
                Ss[row * SSTRf + col + 1]       = sacc[mt][nt][1];
                Ss[(row + 8) * SSTRf + col]     = sacc[mt][nt][2];
                Ss[(row + 8) * SSTRf + col + 1] = sacc[mt][nt][3];
            }
        }
        __syncthreads();   // barrier B

        if (c + 2 < FNIT) f_fillb(ks_b + (c & 1) * FK_W * 4, g_kb32, c + 2, h);
        if (c + 1 < FNIT) f_fillb(vs_b + ((c + 1) & 1) * FV_W * 4, g_v32, c + 1, h);
        asm volatile("cp.async.commit_group;");

        // ---- softmax (fp32, base-2), write P bf16 pairs ----
        {
            float* p0 = &Ss[row2 * SSTRf + part * 16];
            float4 v0 = *(float4*)&p0[0], v1 = *(float4*)&p0[4];
            float4 v2 = *(float4*)&p0[8], v3 = *(float4*)&p0[12];
            float mx = fmaxf(fmaxf(fmaxf(v0.x, v0.y), fmaxf(v0.z, v0.w)),
                             fmaxf(fmaxf(v1.x, v1.y), fmaxf(v1.z, v1.w)));
            mx = fmaxf(mx, fmaxf(fmaxf(fmaxf(v2.x, v2.y), fmaxf(v2.z, v2.w)),
                                 fmaxf(fmaxf(v3.x, v3.y), fmaxf(v3.z, v3.w))));
            mx = fmaxf(mx, __shfl_xor_sync(0xFFFFFFFFu, mx, 1));
            float mnew = fmaxf(m_reg, mx);
            float alpha = ex2(m_reg - mnew);
            m_reg = mnew;

            float e[16];
            e[0]  = ex2(v0.x - mnew); e[1]  = ex2(v0.y - mnew);
            e[2]  = ex2(v0.z - mnew); e[3]  = ex2(v0.w - mnew);
            e[4]  = ex2(v1.x - mnew); e[5]  = ex2(v1.y - mnew);
            e[6]  = ex2(v1.z - mnew); e[7]  = ex2(v1.w - mnew);
            e[8]  = ex2(v2.x - mnew); e[9]  = ex2(v2.y - mnew);
            e[10] = ex2(v2.z - mnew); e[11] = ex2(v2.w - mnew);
            e[12] = ex2(v3.x - mnew); e[13] = ex2(v3.y - mnew);
            e[14] = ex2(v3.z - mnew); e[15] = ex2(v3.w - mnew);
            float ps = 0.f;
            #pragma unroll
            for (int j = 0; j < 16; j++) ps += e[j];
            uint32_t* pp = &Ps[row2 * PS2 + part * 8];
            #pragma unroll
            for (int j = 0; j < 8; j++) pp[j] = packbf(e[2 * j], e[2 * j + 1]);

            ps += __shfl_xor_sync(0xFFFFFFFFu, ps, 1);
            l_reg = l_reg * alpha + ps;
            if (part == 0) alsm[row2] = alpha;
        }

        asm volatile("cp.async.wait_group 1;");
        __syncthreads();   // barrier C

        // ---- PV: O += P[128x32] @ V[32x128], V B-frags via ldmatrix.trans ----
        #pragma unroll
        for (int mt = 0; mt < 4; mt++) {
            int r = wmP * 64 + mt * 16 + gid;
            float al0 = alsm[r], al1 = alsm[r + 8];
            #pragma unroll
            for (int nt = 0; nt < 4; nt++) {
                oacc[mt][nt][0] *= al0; oacc[mt][nt][1] *= al0;
                oacc[mt][nt][2] *= al1; oacc[mt][nt][3] *= al1;
            }
        }
        #pragma unroll
        for (int ks2 = 0; ks2 < 2; ks2++) {
            int kb = ks2 * 16, kp = ks2 * 8;
            uint32_t af[4][4];
            #pragma unroll
            for (int mt = 0; mt < 4; mt++) {
                int m = wmP * 64 + mt * 16 + gid;
                af[mt][0] = Ps[m * PS2 + kp + tig];
                af[mt][1] = Ps[(m + 8) * PS2 + kp + tig];
                af[mt][2] = Ps[m * PS2 + kp + tig + 4];
                af[mt][3] = Ps[(m + 8) * PS2 + kp + tig + 4];
            }
            uint32_t bf[4][2];
            #pragma unroll
            for (int ntp = 0; ntp < 2; ntp++) {
                int n0 = wnP * 32 + ntp * 16;
                uint32_t addr = vbase + (uint32_t)(kb + (lane & 15)) * (VS2 * 4)
                              + (uint32_t)(n0 + ((lane >> 4) << 3)) * 2u;
                uint32_t r0, r1, r2, r3;
                asm volatile(
                    "ldmatrix.sync.aligned.m8n8.x4.trans.shared.b16 {%0,%1,%2,%3}, [%4];"
                    : "=r"(r0), "=r"(r1), "=r"(r2), "=r"(r3) : "r"(addr));
                bf[ntp * 2][0] = r0;     bf[ntp * 2][1] = r1;
                bf[ntp * 2 + 1][0] = r2; bf[ntp * 2 + 1][1] = r3;
            }
            #pragma unroll
            for (int mt = 0; mt < 4; mt++)
                #pragma unroll
                for (int nt = 0; nt < 4; nt++)
                    mma16(oacc[mt][nt], af[mt], bf[nt]);
        }
    }

    if (part == 0) lsm[row2] = l_reg;
    __syncthreads();

    #pragma unroll
    for (int mt = 0; mt < 4; mt++) {
        int r = wmP * 64 + mt * 16 + gid;
        float inv0 = 1.f / lsm[r];
        float inv1 = 1.f / lsm[r + 8];
        int gr0 = q0 + r;
        #pragma unroll
        for (int nt = 0; nt < 4; nt++) {
            int col = h * DHEAD + wnP * 32 + nt * 8 + tig * 2;
            if (gr0 < S_TOK) {
                g_o[(size_t)gr0 * C_DIM + col]     = oacc[mt][nt][0] * inv0;
                g_o[(size_t)gr0 * C_DIM + col + 1] = oacc[mt][nt][1] * inv0;
            }
            if (gr0 + 8 < S_TOK) {
                g_o[(size_t)(gr0 + 8) * C_DIM + col]     = oacc[mt][nt][2] * inv1;
                g_o[(size_t)(gr0 + 8) * C_DIM + col + 1] = oacc[mt][nt][3] * inv1;
            }
        }
    }
}

// ---------------- tf32 GEMM core (output projection; fp32 sources) ----------------
#define GBK    32
#define GSTR   36
#define GBUF_F 9216
#define GEMM_SMEM (3 * GBUF_F * 4)
#define NCH    (C_DIM / GBK)

__device__ __forceinline__ void g_fill(uint32_t sbase, int buf,
                                       const float* __restrict__ A,
                                       const float* __restrict__ Bw,
                                       int m0, int n0, int k0) {
    int tid = threadIdx.x;
    uint32_t bb = sbase + (uint32_t)buf * (GBUF_F * 4);
    #pragma unroll
    for (int it = 0; it < 8; it++) {
        int idx = it * 256 + tid;
        int row = idx >> 3;
        int seg = idx & 7;
        int r   = row & 127;
        bool isB = row >= 128;
        uint32_t dst = bb + (isB ? 18432u : 0u) + (uint32_t)(r * (GSTR * 4) + seg * 16);
        int gr = (isB ? n0 : m0) + r;
        int sz = 16;
        if (!isB && gr >= S_TOK) { sz = 0; gr = 0; }
        const float* src = (isB ? Bw : A) + (size_t)gr * C_DIM + k0 + seg * 4;
        asm volatile("cp.async.cg.shared.global [%0], [%1], 16, %2;"
                     :: "r"(dst), "l"(src), "r"(sz));
    }
}

__device__ __forceinline__ void g_compute(const float* __restrict__ sm, int buf,
                                          int wm, int wn, int gid, int tig,
                                          float (&acc)[4][4][4]) {
    const float* As = sm + buf * GBUF_F;
    const float* Bs = As + 4608;
    #pragma unroll
    for (int ks = 0; ks < 4; ks++) {
        int kb = ks * 8;
        uint32_t af[4][4];
        #pragma unroll
        for (int mt = 0; mt < 4; mt++) {
            int m = wm * 64 + mt * 16 + gid;
            af[mt][0] = __float_as_uint(As[m * GSTR + kb + tig]);
            af[mt][1] = __float_as_uint(As[(m + 8) * GSTR + kb + tig]);
            af[mt][2] = __float_as_uint(As[m * GSTR + kb + 4 + tig]);
            af[mt][3] = __float_as_uint(As[(m + 8) * GSTR + kb + 4 + tig]);
        }
        uint32_t bf[4][2];
        #pragma unroll
        for (int nt = 0; nt < 4; nt++) {
            int n = wn * 32 + nt * 8 + gid;
            bf[nt][0] = __float_as_uint(Bs[n * GSTR + kb + tig]);
            bf[nt][1] = __float_as_uint(Bs[n * GSTR + kb + 4 + tig]);
        }
        #pragma unroll
        for (int mt = 0; mt < 4; mt++)
            #pragma unroll
            for (int nt = 0; nt < 4; nt++)
                mma8(acc[mt][nt], af[mt], bf[nt]);
    }
}

// ---------------- kernel 6: output projection + residual + transpose (tf32) ----------------
#define TSTR 132
__global__ void __launch_bounds__(256, 2) gemm_out_tc(
    const float* __restrict__ Wo, const float* __restrict__ bo,
    const float* __restrict__ x, float* __restrict__ outp) {
    extern __shared__ float gsm[];
    int m0 = blockIdx.y * 128, n0 = blockIdx.x * 128;
    float acc[4][4][4];
    #pragma unroll
    for (int a = 0; a < 4; a++)
        #pragma unroll
        for (int b = 0; b < 4; b++)
            #pragma unroll
            for (int cc = 0; cc < 4; cc++) acc[a][b][cc] = 0.f;

    uint32_t sbase = smem_u32(gsm);
    int tid = threadIdx.x;
    int wid = tid >> 5, lane = tid & 31;
    int wm = wid >> 2, wn = wid & 3;
    int gid = lane >> 2, tig = lane & 3;

    g_fill(sbase, 0, g_o, Wo, m0, n0, 0);
    asm volatile("cp.async.commit_group;");
    g_fill(sbase, 1, g_o, Wo, m0, n0, GBK);
    asm volatile("cp.async.commit_group;");

    int buf = 0, nbuf = 2;
    for (int c = 0; c < NCH; c++) {
        asm volatile("cp.async.wait_group 1;");
        __syncthreads();
        if (c + 2 < NCH) g_fill(sbase, nbuf, g_o, Wo, m0, n0, (c + 2) * GBK);
        asm volatile("cp.async.commit_group;");
        g_compute(gsm, buf, wm, wn, gid, tig, acc);
        buf = (buf == 2) ? 0 : buf + 1;
        nbuf = (nbuf == 2) ? 0 : nbuf + 1;
    }

    asm volatile("cp.async.wait_group 0;");
    __syncthreads();

    // smem transpose staging for coalesced column writes
    #pragma unroll
    for (int mt = 0; mt < 4; mt++) {
        int row = wm * 64 + mt * 16 + gid;
        #pragma unroll
        for (int nt = 0; nt < 4; nt++) {
            int col = wn * 32 + nt * 8 + tig * 2;
            gsm[col * TSTR + row]           = acc[mt][nt][0];
            gsm[(col + 1) * TSTR + row]     = acc[mt][nt][1];
            gsm[col * TSTR + row + 8]       = acc[mt][nt][2];
            gsm[(col + 1) * TSTR + row + 8] = acc[mt][nt][3];
        }
    }
    __syncthreads();

    #pragma unroll
    for (int cc2 = 0; cc2 < 16; cc2++) {
        int col = wid * 16 + cc2;
        int gcol = n0 + col;
        float b = bo[gcol];
        int grow = m0 + lane * 4;
        if (grow < S_TOK) {
            float4 a = *(float4*)&gsm[col * TSTR + lane * 4];
            size_t gi = (size_t)gcol * S_TOK + grow;
            float4 xv = *(const float4*)&x[gi];
            float4 o;
            o.x = xv.x + b + a.x; o.y = xv.y + b + a.y;
            o.z = xv.z + b + a.z; o.w = xv.w + b + a.w;
            *(float4*)&outp[gi] = o;
        }
    }
}

// ---------------- launcher ----------------
extern "C" void kernel_launch(void* const* d_in, const int* in_sizes, int n_in,
                              void* d_out, int out_size) {
    const float* x  = (const float*)d_in[0];
    const float* Wq = (const float*)d_in[1];
    const float* bq = (const float*)d_in[2];
    const float* Wk = (const float*)d_in[3];
    const float* bk = (const float*)d_in[4];
    const float* Wv = (const float*)d_in[5];
    const float* bv = (const float*)d_in[6];
    const float* Wo = (const float*)d_in[7];
    const float* bo = (const float*)d_in[8];
    const float* gq = (const float*)d_in[9];
    const float* gk = (const float*)d_in[10];
    float* out = (float*)d_out;

    ln_transpose_kernel<<<S_TOK / 32, 256>>>(x);
    rope_table_kernel<<<(S_TOK * HALF + 255) / 256, 256>>>();
    convert_w_kernel<<<dim3(C_DIM * C_DIM / 4 / 256, 3), 256>>>(Wq, Wk, Wv);

    cudaFuncSetAttribute(gemm_qkv_b, cudaFuncAttributeMaxDynamicSharedMemorySize, GEMMB_SMEM);
    cudaFuncSetAttribute(gemm_out_tc, cudaFuncAttributeMaxDynamicSharedMemorySize, GEMM_SMEM);
    cudaFuncSetAttribute(flash_kernel, cudaFuncAttributeMaxDynamicSharedMemorySize, FLASH_SMEM);

    gemm_qkv_b<<<dim3(C_DIM / 128, (S_TOK + 127) / 128, 3), 256, GEMMB_SMEM>>>(bq, bk, bv);
    rms_rope_kernel<<<dim3(S_TOK, 2), 256>>>(gq, gk);

    flash_kernel<<<dim3((S_TOK + 127) / 128, NHEAD), 256, FLASH_SMEM>>>();

    gemm_out_tc<<<dim3(C_DIM / 128, (S_TOK + 127) / 128), 256, GEMM_SMEM>>>(Wo, bo, x, out);
}

// round 10
// speedup vs baseline: 9.6960x; 1.1094x over previous
#include <cuda_runtime.h>
#include <cuda_bf16.h>
#include <math.h>
#include <stdint.h>

#define S_TOK 3872
#define C_DIM 1536
#define NHEAD 12
#define DHEAD 128
#define HALF  64
#define T_DIM 8
#define H_DIM 22
#define W_DIM 22
#define CPAIR (C_DIM / 2)   // 768 uint32 pairs per row

// ---------------- scratch (device globals; no runtime allocation) ----------------
__device__ __nv_bfloat16 g_xn[S_TOK * C_DIM];
__device__ __nv_bfloat16 g_wq[C_DIM * C_DIM];
__device__ __nv_bfloat16 g_wk[C_DIM * C_DIM];
__device__ __nv_bfloat16 g_wv[C_DIM * C_DIM];
__device__ __nv_bfloat16 g_wo[C_DIM * C_DIM];
__device__ float    g_q [S_TOK * C_DIM];
__device__ float    g_k [S_TOK * C_DIM];
__device__ uint32_t g_v32 [S_TOK * CPAIR];
__device__ uint32_t g_qb32[S_TOK * CPAIR];
__device__ uint32_t g_kb32[S_TOK * CPAIR];
__device__ uint32_t g_ob32[S_TOK * CPAIR];
__device__ float g_cos[S_TOK * HALF];
__device__ float g_sin[S_TOK * HALF];

// ---------------- helpers ----------------
__device__ __forceinline__ uint32_t smem_u32(const void* p) {
    uint32_t a;
    asm("{ .reg .u64 t; cvta.to.shared.u64 t, %1; cvt.u32.u64 %0, t; }" : "=r"(a) : "l"(p));
    return a;
}

// bf16 m16n8k16
__device__ __forceinline__ void mma16(float* c, const uint32_t* a, const uint32_t* b) {
    asm volatile(
        "mma.sync.aligned.m16n8k16.row.col.f32.bf16.bf16.f32 "
        "{%0,%1,%2,%3}, {%4,%5,%6,%7}, {%8,%9}, {%0,%1,%2,%3};"
        : "+f"(c[0]), "+f"(c[1]), "+f"(c[2]), "+f"(c[3])
        : "r"(a[0]), "r"(a[1]), "r"(a[2]), "r"(a[3]), "r"(b[0]), "r"(b[1]));
}

__device__ __forceinline__ void ldmx4(uint32_t* r, uint32_t addr) {
    asm volatile("ldmatrix.sync.aligned.m8n8.x4.shared.b16 {%0,%1,%2,%3}, [%4];"
                 : "=r"(r[0]), "=r"(r[1]), "=r"(r[2]), "=r"(r[3]) : "r"(addr));
}

__device__ __forceinline__ uint32_t packbf(float lo, float hi) {
    uint32_t r;
    asm("cvt.rn.bf16x2.f32 %0, %1, %2;" : "=r"(r) : "f"(hi), "f"(lo));
    return r;
}

__device__ __forceinline__ float ex2(float x) {
    float y;
    asm("ex2.approx.ftz.f32 %0, %1;" : "=f"(y) : "f"(x));
    return y;
}

// ---------------- kernel 1: layernorm + transpose -> bf16 g_xn ----------------
__global__ void __launch_bounds__(256) ln_transpose_kernel(const float* __restrict__ x) {
    int s0 = blockIdx.x * 32;
    int sl = threadIdx.x & 31;
    int cg = threadIdx.x >> 5;

    float sum = 0.f, sq = 0.f;
    for (int c = cg; c < C_DIM; c += 8) {
        float v = x[c * S_TOK + s0 + sl];
        sum += v; sq += v * v;
    }
    __shared__ float ssum[8][32], ssq[8][32];
    ssum[cg][sl] = sum; ssq[cg][sl] = sq;
    __syncthreads();

    __shared__ float mean_s[32], rstd_s[32];
    if (cg == 0) {
        float a = 0.f, b = 0.f;
        #pragma unroll
        for (int g = 0; g < 8; g++) { a += ssum[g][sl]; b += ssq[g][sl]; }
        float m = a / C_DIM;
        float var = b / C_DIM - m * m;
        mean_s[sl] = m;
        rstd_s[sl] = rsqrtf(var + 1e-6f);
    }
    __syncthreads();

    __shared__ float tile[32][33];
    for (int c0 = 0; c0 < C_DIM; c0 += 32) {
        #pragma unroll
        for (int r = 0; r < 4; r++) {
            int cl = cg + 8 * r;
            tile[cl][sl] = x[(c0 + cl) * S_TOK + s0 + sl];
        }
        __syncthreads();
        #pragma unroll
        for (int r = 0; r < 4; r++) {
            int srow = cg + 8 * r;
            g_xn[(s0 + srow) * C_DIM + c0 + sl] =
                __float2bfloat16((tile[sl][srow] - mean_s[srow]) * rstd_s[srow]);
        }
        __syncthreads();
    }
}

// ---------------- kernel 2: RoPE cos/sin table ----------------
__global__ void rope_table_kernel() {
    int idx = blockIdx.x * blockDim.x + threadIdx.x;
    if (idx >= S_TOK * HALF) return;
    int s = idx >> 6, j = idx & 63;
    int t  = s / (H_DIM * W_DIM);
    int rem = s % (H_DIM * W_DIM);
    int hh = rem / W_DIM, ww = rem % W_DIM;
    const double LT = log(10000.0);
    double a;
    if (j < 22)      a = (double)t  * exp(-(double)j        / 22.0 * LT);
    else if (j < 43) a = (double)hh * exp(-(double)(j - 22) / 21.0 * LT);
    else             a = (double)ww * exp(-(double)(j - 43) / 21.0 * LT);
    g_cos[idx] = (float)cos(a);
    g_sin[idx] = (float)sin(a);
}

// ---------------- kernel 2b: convert Wq/Wk/Wv/Wo to bf16 ----------------
__global__ void __launch_bounds__(256) convert_w_kernel(
    const float* __restrict__ Wq, const float* __restrict__ Wk,
    const float* __restrict__ Wv, const float* __restrict__ Wo) {
    int idx = blockIdx.x * 256 + threadIdx.x;           // float4 index
    const float* src = (blockIdx.y == 0) ? Wq : (blockIdx.y == 1) ? Wk
                     : (blockIdx.y == 2) ? Wv : Wo;
    __nv_bfloat16* dst = (blockIdx.y == 0) ? g_wq : (blockIdx.y == 1) ? g_wk
                       : (blockIdx.y == 2) ? g_wv : g_wo;
    float4 v = *(const float4*)&src[(size_t)idx * 4];
    uint2 o;
    o.x = packbf(v.x, v.y);
    o.y = packbf(v.z, v.w);
    *(uint2*)&dst[(size_t)idx * 4] = o;
}

// ---------------- bf16 GEMM core (3-stage cp.async, BK=64, ldmatrix frags) ----------------
#define BBK    64
#define BSTR   36            // uint32 pair stride (32 used + 4 pad); 36 mod 32 = 4
#define BBUF_W 9216
#define GEMMB_SMEM (3 * BBUF_W * 4)
#define BNCH   (C_DIM / BBK) // 24

__device__ __forceinline__ void gb_fill(uint32_t sbase, int buf,
                                        const __nv_bfloat16* __restrict__ A,
                                        const __nv_bfloat16* __restrict__ Bw,
                                        int m0, int n0, int k0) {
    int tid = threadIdx.x;
    uint32_t bb = sbase + (uint32_t)buf * (BBUF_W * 4);
    #pragma unroll
    for (int it = 0; it < 8; it++) {
        int idx = it * 256 + tid;
        int row = idx >> 3;
        int seg = idx & 7;               // 16B = 8 bf16
        int r   = row & 127;
        bool isB = row >= 128;
        uint32_t dst = bb + (isB ? 18432u : 0u) + (uint32_t)(r * (BSTR * 4) + seg * 16);
        int gr = (isB ? n0 : m0) + r;
        int sz = 16;
        if (!isB && gr >= S_TOK) { sz = 0; gr = 0; }
        const __nv_bfloat16* src = (isB ? Bw : A) + (size_t)gr * C_DIM + k0 + seg * 8;
        asm volatile("cp.async.cg.shared.global [%0], [%1], 16, %2;"
                     :: "r"(dst), "l"(src), "r"(sz));
    }
}

// fragment loads via ldmatrix.x4; thread-role indices precomputed by caller:
// arow = (lane>>3 & 1)*8 + (lane&7), acolw = (lane>>4)*4  (A matrices 0..3 order)
// brow = (lane>>4)*8 + (lane&7),     bcolw = (lane>>3 & 1)*4
__device__ __forceinline__ void gb_compute(uint32_t abase, uint32_t bbase,
                                           int wm, int wn,
                                           int arow, int acolw, int brow, int bcolw,
                                           float (&acc)[4][4][4]) {
    #pragma unroll
    for (int ks = 0; ks < 4; ks++) {
        int kp = ks * 8;
        uint32_t af[4][4];
        #pragma unroll
        for (int mt = 0; mt < 4; mt++)
            ldmx4(af[mt], abase + (uint32_t)((wm * 64 + mt * 16 + arow) * BSTR + kp + acolw) * 4u);
        uint32_t bf[4][2];
        #pragma unroll
        for (int pr = 0; pr < 2; pr++) {
            uint32_t t[4];
            ldmx4(t, bbase + (uint32_t)((wn * 32 + pr * 16 + brow) * BSTR + kp + bcolw) * 4u);
            bf[pr * 2][0] = t[0];     bf[pr * 2][1] = t[1];
            bf[pr * 2 + 1][0] = t[2]; bf[pr * 2 + 1][1] = t[3];
        }
        #pragma unroll
        for (int mt = 0; mt < 4; mt++)
            #pragma unroll
            for (int nt = 0; nt < 4; nt++)
                mma16(acc[mt][nt], af[mt], bf[nt]);
    }
}

// ---------------- kernel 3: Q/K/V projections (bf16) ----------------
__global__ void __launch_bounds__(256, 2) gemm_qkv_b(
    const float* __restrict__ bq, const float* __restrict__ bk,
    const float* __restrict__ bv) {
    extern __shared__ uint32_t gsb[];
    const __nv_bfloat16* Wm;
    const float* bias;
    if (blockIdx.z == 0)      { Wm = g_wq; bias = bq; }
    else if (blockIdx.z == 1) { Wm = g_wk; bias = bk; }
    else                      { Wm = g_wv; bias = bv; }

    int m0 = blockIdx.y * 128, n0 = blockIdx.x * 128;
    float acc[4][4][4];
    #pragma unroll
    for (int a = 0; a < 4; a++)
        #pragma unroll
        for (int b = 0; b < 4; b++)
            #pragma unroll
            for (int cc = 0; cc < 4; cc++) acc[a][b][cc] = 0.f;

    uint32_t sbase = smem_u32(gsb);
    int tid = threadIdx.x;
    int wid = tid >> 5, lane = tid & 31;
    int wm = wid >> 2, wn = wid & 3;
    int gid = lane >> 2, tig = lane & 3;
    int arow = ((lane >> 3) & 1) * 8 + (lane & 7), acolw = (lane >> 4) * 4;
    int brow = (lane >> 4) * 8 + (lane & 7), bcolw = ((lane >> 3) & 1) * 4;

    gb_fill(sbase, 0, g_xn, Wm, m0, n0, 0);
    asm volatile("cp.async.commit_group;");
    gb_fill(sbase, 1, g_xn, Wm, m0, n0, BBK);
    asm volatile("cp.async.commit_group;");

    int buf = 0, nbuf = 2;
    for (int c = 0; c < BNCH; c++) {
        asm volatile("cp.async.wait_group 1;");
        __syncthreads();
        if (c + 2 < BNCH) gb_fill(sbase, nbuf, g_xn, Wm, m0, n0, (c + 2) * BBK);
        asm volatile("cp.async.commit_group;");
        uint32_t abase = sbase + (uint32_t)buf * (BBUF_W * 4);
        gb_compute(abase, abase + 18432u, wm, wn, arow, acolw, brow, bcolw, acc);
        buf = (buf == 2) ? 0 : buf + 1;
        nbuf = (nbuf == 2) ? 0 : nbuf + 1;
    }

    #pragma unroll
    for (int mt = 0; mt < 4; mt++) {
        int row = m0 + wm * 64 + mt * 16 + gid;
        #pragma unroll
        for (int nt = 0; nt < 4; nt++) {
            int col = n0 + wn * 32 + nt * 8 + tig * 2;
            float b0 = bias[col], b1 = bias[col + 1];
            if (blockIdx.z == 2) {
                if (row < S_TOK)
                    g_v32[(size_t)row * CPAIR + (col >> 1)] =
                        packbf(acc[mt][nt][0] + b0, acc[mt][nt][1] + b1);
                if (row + 8 < S_TOK)
                    g_v32[(size_t)(row + 8) * CPAIR + (col >> 1)] =
                        packbf(acc[mt][nt][2] + b0, acc[mt][nt][3] + b1);
            } else {
                float* out = (blockIdx.z == 0) ? g_q : g_k;
                if (row < S_TOK) {
                    out[(size_t)row * C_DIM + col]     = acc[mt][nt][0] + b0;
                    out[(size_t)row * C_DIM + col + 1] = acc[mt][nt][1] + b1;
                }
                if (row + 8 < S_TOK) {
                    out[(size_t)(row + 8) * C_DIM + col]     = acc[mt][nt][2] + b0;
                    out[(size_t)(row + 8) * C_DIM + col + 1] = acc[mt][nt][3] + b1;
                }
            }
        }
    }
}

// ---------------- kernel 4: RMSNorm + RoPE -> bf16 pairs ----------------
__global__ void __launch_bounds__(256) rms_rope_kernel(const float* __restrict__ gq,
                                                       const float* __restrict__ gk) {
    int s = blockIdx.x;
    const float* data = (blockIdx.y == 0) ? g_q : g_k;
    const float* g    = (blockIdx.y == 0) ? gq  : gk;
    uint32_t* outp    = (blockIdx.y == 0) ? g_qb32 : g_kb32;
    float s2 = (blockIdx.y == 0) ? 0.08838834764831845f * 1.44269504088896341f : 1.f;

    float ss = 0.f;
    for (int c = threadIdx.x; c < C_DIM; c += 256) {
        float v = data[(size_t)s * C_DIM + c];
        ss += v * v;
    }
    __shared__ float red[256];
    red[threadIdx.x] = ss;
    __syncthreads();
    for (int off = 128; off > 0; off >>= 1) {
        if (threadIdx.x < off) red[threadIdx.x] += red[threadIdx.x + off];
        __syncthreads();
    }
    float rs = rsqrtf(red[0] / C_DIM + 1e-6f);

    for (int p = threadIdx.x; p < NHEAD * HALF; p += 256) {
        int head = p >> 6, j = p & 63;
        int cr = head * DHEAD + 2 * j, ci = cr + 1;
        float xr = data[(size_t)s * C_DIM + cr] * rs * g[cr];
        float xi = data[(size_t)s * C_DIM + ci] * rs * g[ci];
        float co = g_cos[s * HALF + j], si = g_sin[s * HALF + j];
        float orr = (xr * co - xi * si) * s2;
        float oii = (xr * si + xi * co) * s2;
        outp[(size_t)s * CPAIR + head * HALF + j] = packbf(orr, oii);
    }
}

// ---------------- kernel 5: flash attention (bf16 mma + ldmatrix) ----------------
#define FBK   32
#define FNIT  (S_TOK / FBK)   // 121
#define QS2   68
#define KS2   68
#define VS2   68
#define SSTRf 36
#define PS2   20
#define FQ_W  (128 * QS2)
#define FK_W  (FBK * KS2)
#define FV_W  (FBK * VS2)
#define FS_W  (128 * SSTRf)
#define FP_W  (128 * PS2)
#define FLASH_W (FQ_W + 2 * FK_W + 2 * FV_W + FS_W + FP_W + 256)
#define FLASH_SMEM (FLASH_W * 4)

__device__ __forceinline__ void f_fillb(uint32_t dstbase, const uint32_t* __restrict__ src,
                                        int kc, int h) {
    int tid = threadIdx.x;
    #pragma unroll
    for (int it = 0; it < 2; it++) {
        int idx = it * 256 + tid;
        int row = idx >> 4, seg = idx & 15;
        uint32_t dst = dstbase + (uint32_t)(row * KS2 + seg * 4) * 4u;
        const uint32_t* s = src + (size_t)(kc * FBK + row) * CPAIR + h * HALF + seg * 4;
        asm volatile("cp.async.cg.shared.global [%0], [%1], 16;" :: "r"(dst), "l"(s));
    }
}

__global__ void __launch_bounds__(256, 2) flash_kernel() {
    extern __shared__ uint32_t fsw[];
    float*    Ss = (float*)(fsw + FQ_W + 2 * FK_W + 2 * FV_W);
    float* alsm  = (float*)(fsw + FQ_W + 2 * FK_W + 2 * FV_W + FS_W + FP_W);
    float* lsm   = alsm + 128;

    uint32_t sb   = smem_u32(fsw);
    uint32_t ks_b = sb + FQ_W * 4;
    uint32_t vs_b = ks_b + 2 * FK_W * 4;
    uint32_t ps_b = vs_b + 2 * FV_W * 4 + FS_W * 4;

    int q0 = blockIdx.x * 128;
    int h  = blockIdx.y;
    int tid = threadIdx.x;
    int wid = tid >> 5, lane = tid & 31;
    int gid = lane >> 2, tig = lane & 3;
    int arow = ((lane >> 3) & 1) * 8 + (lane & 7), acolw = (lane >> 4) * 4;
    int brow = (lane >> 4) * 8 + (lane & 7), bcolw = ((lane >> 3) & 1) * 4;

    // Q fill (bf16 pairs, already scaled)
    #pragma unroll
    for (int it = 0; it < 8; it++) {
        int idx = it * 256 + tid;
        int row = idx >> 4, seg = idx & 15;
        uint32_t dst = sb + (uint32_t)(row * QS2 + seg * 4) * 4u;
        int gr = q0 + row;
        int sz = (gr < S_TOK) ? 16 : 0;
        if (gr >= S_TOK) gr = 0;
        const uint32_t* s = g_qb32 + (size_t)gr * CPAIR + h * HALF + seg * 4;
        asm volatile("cp.async.cg.shared.global [%0], [%1], 16, %2;"
                     :: "r"(dst), "l"(s), "r"(sz));
    }

    f_fillb(ks_b, g_kb32, 0, h);
    f_fillb(vs_b, g_v32, 0, h);
    asm volatile("cp.async.commit_group;");
    f_fillb(ks_b + FK_W * 4, g_kb32, 1, h);
    asm volatile("cp.async.commit_group;");

    int row2 = tid >> 1, part = tid & 1;
    float m_reg = -1e30f, l_reg = 0.f;

    int wmP = wid >> 2, wnP = wid & 3;
    float oacc[4][4][4];
    #pragma unroll
    for (int a = 0; a < 4; a++)
        #pragma unroll
        for (int b = 0; b < 4; b++)
            #pragma unroll
            for (int cc = 0; cc < 4; cc++) oacc[a][b][cc] = 0.f;

    int wmS = wid >> 1, wnS = wid & 1;

    asm volatile("cp.async.wait_group 1;");
    __syncthreads();

    for (int c = 0; c < FNIT; c++) {
        uint32_t kb_b  = ks_b + (uint32_t)(c & 1) * FK_W * 4;
        uint32_t vbase = vs_b + (uint32_t)(c & 1) * FV_W * 4;

        // ---- S = Q @ K^T : [128][32] (8 k16-steps, ldmatrix frags) ----
        float sacc[2][2][4];
        #pragma unroll
        for (int a = 0; a < 2; a++)
            #pragma unroll
            for (int b = 0; b < 2; b++)
                #pragma unroll
                for (int cc = 0; cc < 4; cc++) sacc[a][b][cc] = 0.f;

        #pragma unroll
        for (int ks = 0; ks < 8; ks++) {
            int kp = ks * 8;
            uint32_t af[2][4];
            #pragma unroll
            for (int mt = 0; mt < 2; mt++)
                ldmx4(af[mt], sb + (uint32_t)((wmS * 32 + mt * 16 + arow) * QS2 + kp + acolw) * 4u);
            uint32_t t[4];
            ldmx4(t, kb_b + (uint32_t)((wnS * 16 + brow) * KS2 + kp + bcolw) * 4u);
            uint32_t bf0[2] = {t[0], t[1]}, bf1[2] = {t[2], t[3]};
            #pragma unroll
            for (int mt = 0; mt < 2; mt++) {
                mma16(sacc[mt][0], af[mt], bf0);
                mma16(sacc[mt][1], af[mt], bf1);
            }
        }
        #pragma unroll
        for (int mt = 0; mt < 2; mt++) {
            int row = wmS * 32 + mt * 16 + gid;
            #pragma unroll
            for (int nt = 0; nt < 2; nt++) {
                int col = wnS * 16 + nt * 8 + tig * 2;
                Ss[row * SSTRf + col]           = sacc[mt][nt][0];
                Ss[row * SSTRf + col + 1]       = sacc[mt][nt][1];
                Ss[(row + 8) * SSTRf + col]     = sacc[mt][nt][2];
                Ss[(row + 8) * SSTRf + col + 1] = sacc[mt][nt][3];
            }
        }
        __syncthreads();

        if (c + 2 < FNIT) f_fillb(ks_b + (c & 1) * FK_W * 4, g_kb32, c + 2, h);
        if (c + 1 < FNIT) f_fillb(vs_b + ((c + 1) & 1) * FV_W * 4, g_v32, c + 1, h);
        asm volatile("cp.async.commit_group;");

        // ---- softmax (fp32, base-2), write P bf16 pairs ----
        {
            uint32_t* Ps = fsw + FQ_W + 2 * FK_W + 2 * FV_W + FS_W;
            float* p0 = &Ss[row2 * SSTRf + part * 16];
            float4 v0 = *(float4*)&p0[0], v1 = *(float4*)&p0[4];
            float4 v2 = *(float4*)&p0[8], v3 = *(float4*)&p0[12];
            float mx = fmaxf(fmaxf(fmaxf(v0.x, v0.y), fmaxf(v0.z, v0.w)),
                             fmaxf(fmaxf(v1.x, v1.y), fmaxf(v1.z, v1.w)));
            mx = fmaxf(mx, fmaxf(fmaxf(fmaxf(v2.x, v2.y), fmaxf(v2.z, v2.w)),
                                 fmaxf(fmaxf(v3.x, v3.y), fmaxf(v3.z, v3.w))));
            mx = fmaxf(mx, __shfl_xor_sync(0xFFFFFFFFu, mx, 1));
            float mnew = fmaxf(m_reg, mx);
            float alpha = ex2(m_reg - mnew);
            m_reg = mnew;

            float e[16];
            e[0]  = ex2(v0.x - mnew); e[1]  = ex2(v0.y - mnew);
            e[2]  = ex2(v0.z - mnew); e[3]  = ex2(v0.w - mnew);
            e[4]  = ex2(v1.x - mnew); e[5]  = ex2(v1.y - mnew);
            e[6]  = ex2(v1.z - mnew); e[7]  = ex2(v1.w - mnew);
            e[8]  = ex2(v2.x - mnew); e[9]  = ex2(v2.y - mnew);
            e[10] = ex2(v2.z - mnew); e[11] = ex2(v2.w - mnew);
            e[12] = ex2(v3.x - mnew); e[13] = ex2(v3.y - mnew);
            e[14] = ex2(v3.z - mnew); e[15] = ex2(v3.w - mnew);
            float ps = 0.f;
            #pragma unroll
            for (int j = 0; j < 16; j++) ps += e[j];
            uint32_t* pp = &Ps[row2 * PS2 + part * 8];
            #pragma unroll
            for (int j = 0; j < 8; j++) pp[j] = packbf(e[2 * j], e[2 * j + 1]);

            ps += __shfl_xor_sync(0xFFFFFFFFu, ps, 1);
            l_reg = l_reg * alpha + ps;
            if (part == 0) alsm[row2] = alpha;
        }

        asm volatile("cp.async.wait_group 1;");
        __syncthreads();

        // ---- PV: O += P[128x32] @ V[32x128] ----
        #pragma unroll
        for (int mt = 0; mt < 4; mt++) {
            int r = wmP * 64 + mt * 16 + gid;
            float al0 = alsm[r], al1 = alsm[r + 8];
            #pragma unroll
            for (int nt = 0; nt < 4; nt++) {
                oacc[mt][nt][0] *= al0; oacc[mt][nt][1] *= al0;
                oacc[mt][nt][2] *= al1; oacc[mt][nt][3] *= al1;
            }
        }
        #pragma unroll
        for (int ks2 = 0; ks2 < 2; ks2++) {
            int kb = ks2 * 16, kp = ks2 * 8;
            uint32_t af[4][4];
            #pragma unroll
            for (int mt = 0; mt < 4; mt++)
                ldmx4(af[mt], ps_b + (uint32_t)((wmP * 64 + mt * 16 + arow) * PS2 + kp + acolw) * 4u);
            uint32_t bf[4][2];
            #pragma unroll
            for (int ntp = 0; ntp < 2; ntp++) {
                int n0 = wnP * 32 + ntp * 16;
                uint32_t addr = vbase + (uint32_t)(kb + (lane & 15)) * (VS2 * 4)
                              + (uint32_t)(n0 + ((lane >> 4) << 3)) * 2u;
                uint32_t r0, r1, r2, r3;
                asm volatile(
                    "ldmatrix.sync.aligned.m8n8.x4.trans.shared.b16 {%0,%1,%2,%3}, [%4];"
                    : "=r"(r0), "=r"(r1), "=r"(r2), "=r"(r3) : "r"(addr));
                bf[ntp * 2][0] = r0;     bf[ntp * 2][1] = r1;
                bf[ntp * 2 + 1][0] = r2; bf[ntp * 2 + 1][1] = r3;
            }
            #pragma unroll
            for (int mt = 0; mt < 4; mt++)
                #pragma unroll
                for (int nt = 0; nt < 4; nt++)
                    mma16(oacc[mt][nt], af[mt], bf[nt]);
        }
    }

    if (part == 0) lsm[row2] = l_reg;
    __syncthreads();

    // epilogue -> bf16 pairs (feeds bf16 output projection)
    #pragma unroll
    for (int mt = 0; mt < 4; mt++) {
        int r = wmP * 64 + mt * 16 + gid;
        float inv0 = 1.f / lsm[r];
        float inv1 = 1.f / lsm[r + 8];
        int gr0 = q0 + r;
        #pragma unroll
        for (int nt = 0; nt < 4; nt++) {
            int col = h * DHEAD + wnP * 32 + nt * 8 + tig * 2;
            if (gr0 < S_TOK)
                g_ob32[(size_t)gr0 * CPAIR + (col >> 1)] =
                    packbf(oacc[mt][nt][0] * inv0, oacc[mt][nt][1] * inv0);
            if (gr0 + 8 < S_TOK)
                g_ob32[(size_t)(gr0 + 8) * CPAIR + (col >> 1)] =
                    packbf(oacc[mt][nt][2] * inv1, oacc[mt][nt][3] * inv1);
        }
    }
}

// ---------------- kernel 6: output projection (bf16) + residual + transpose ----------------
#define TSTR 132
__global__ void __launch_bounds__(256, 2) gemm_out_b(
    const float* __restrict__ bo, const float* __restrict__ x,
    float* __restrict__ outp) {
    extern __shared__ uint32_t gsb[];
    const __nv_bfloat16* Aob = (const __nv_bfloat16*)g_ob32;
    int m0 = blockIdx.y * 128, n0 = blockIdx.x * 128;
    float acc[4][4][4];
    #pragma unroll
    for (int a = 0; a < 4; a++)
        #pragma unroll
        for (int b = 0; b < 4; b++)
            #pragma unroll
            for (int cc = 0; cc < 4; cc++) acc[a][b][cc] = 0.f;

    uint32_t sbase = smem_u32(gsb);
    int tid = threadIdx.x;
    int wid = tid >> 5, lane = tid & 31;
    int wm = wid >> 2, wn = wid & 3;
    int gid = lane >> 2, tig = lane & 3;
    int arow = ((lane >> 3) & 1) * 8 + (lane & 7), acolw = (lane >> 4) * 4;
    int brow = (lane >> 4) * 8 + (lane & 7), bcolw = ((lane >> 3) & 1) * 4;

    gb_fill(sbase, 0, Aob, g_wo, m0, n0, 0);
    asm volatile("cp.async.commit_group;");
    gb_fill(sbase, 1, Aob, g_wo, m0, n0, BBK);
    asm volatile("cp.async.commit_group;");

    int buf = 0, nbuf = 2;
    for (int c = 0; c < BNCH; c++) {
        asm volatile("cp.async.wait_group 1;");
        __syncthreads();
        if (c + 2 < BNCH) gb_fill(sbase, nbuf, Aob, g_wo, m0, n0, (c + 2) * BBK);
        asm volatile("cp.async.commit_group;");
        uint32_t abase = sbase + (uint32_t)buf * (BBUF_W * 4);
        gb_compute(abase, abase + 18432u, wm, wn, arow, acolw, brow, bcolw, acc);
        buf = (buf == 2) ? 0 : buf + 1;
        nbuf = (nbuf == 2) ? 0 : nbuf + 1;
    }

    asm volatile("cp.async.wait_group 0;");
    __syncthreads();

    // smem transpose staging for coalesced column-major writes
    float* gsm = (float*)gsb;
    #pragma unroll
    for (int mt = 0; mt < 4; mt++) {
        int row = wm * 64 + mt * 16 + gid;
        #pragma unroll
        for (int nt = 0; nt < 4; nt++) {
            int col = wn * 32 + nt * 8 + tig * 2;
            gsm[col * TSTR + row]           = acc[mt][nt][0];
            gsm[(col + 1) * TSTR + row]     = acc[mt][nt][1];
            gsm[col * TSTR + row + 8]       = acc[mt][nt][2];
            gsm[(col + 1) * TSTR + row + 8] = acc[mt][nt][3];
        }
    }
    __syncthreads();

    #pragma unroll
    for (int cc2 = 0; cc2 < 16; cc2++) {
        int col = wid * 16 + cc2;
        int gcol = n0 + col;
        float b = bo[gcol];
        int grow = m0 + lane * 4;
        if (grow < S_TOK) {
            float4 a = *(float4*)&gsm[col * TSTR + lane * 4];
            size_t gi = (size_t)gcol * S_TOK + grow;
            float4 xv = *(const float4*)&x[gi];
            float4 o;
            o.x = xv.x + b + a.x; o.y = xv.y + b + a.y;
            o.z = xv.z + b + a.z; o.w = xv.w + b + a.w;
            *(float4*)&outp[gi] = o;
        }
    }
}

// ---------------- launcher ----------------
extern "C" void kernel_launch(void* const* d_in, const int* in_sizes, int n_in,
                              void* d_out, int out_size) {
    const float* x  = (const float*)d_in[0];
    const float* Wq = (const float*)d_in[1];
    const float* bq = (const float*)d_in[2];
    const float* Wk = (const float*)d_in[3];
    const float* bk = (const float*)d_in[4];
    const float* Wv = (const float*)d_in[5];
    const float* bv = (const float*)d_in[6];
    const float* Wo = (const float*)d_in[7];
    const float* bo = (const float*)d_in[8];
    const float* gq = (const float*)d_in[9];
    const float* gk = (const float*)d_in[10];
    float* out = (float*)d_out;

    ln_transpose_kernel<<<S_TOK / 32, 256>>>(x);
    rope_table_kernel<<<(S_TOK * HALF + 255) / 256, 256>>>();
    convert_w_kernel<<<dim3(C_DIM * C_DIM / 4 / 256, 4), 256>>>(Wq, Wk, Wv, Wo);

    cudaFuncSetAttribute(gemm_qkv_b, cudaFuncAttributeMaxDynamicSharedMemorySize, GEMMB_SMEM);
    cudaFuncSetAttribute(gemm_out_b, cudaFuncAttributeMaxDynamicSharedMemorySize, GEMMB_SMEM);
    cudaFuncSetAttribute(flash_kernel, cudaFuncAttributeMaxDynamicSharedMemorySize, FLASH_SMEM);

    gemm_qkv_b<<<dim3(C_DIM / 128, (S_TOK + 127) / 128, 3), 256, GEMMB_SMEM>>>(bq, bk, bv);
    rms_rope_kernel<<<dim3(S_TOK, 2), 256>>>(gq, gk);

    flash_kernel<<<dim3((S_TOK + 127) / 128, NHEAD), 256, FLASH_SMEM>>>();

    gemm_out_b<<<dim3(C_DIM / 128, (S_TOK + 127) / 128), 256, GEMMB_SMEM>>>(bo, x, out);
}